// round 1
// baseline (speedup 1.0000x reference)
#include <cuda_runtime.h>
#include <math.h>

// Problem constants (fixed by the reference setup_inputs)
#define NN 8192            // number of nodes
#define FIN 512
#define FH 256
#define FOUT 64
#define NEGV (-9e15f)
#define LRELU_A 0.2f

// ---------------- scratch (no allocations allowed) ----------------
__device__ float g_h1[NN * FH];     // layer-1 linear output
__device__ float g_y1[NN * FH];     // elu(elu(attn1 @ h1)) = layer-2 input
__device__ float g_h2[NN * FOUT];   // layer-2 linear output
__device__ float g_s1[NN], g_t1[NN];
__device__ float g_s2[NN], g_t2[NN];

__device__ __forceinline__ float elu1(float x) { return x > 0.f ? x : expm1f(x); }

// =================================================================
// GEMM: C[M,N] = A[M,K] @ W[N,K]^T + bias[N]     (both K-major, "NT")
// BM=128, BN=64, BK=16, 256 threads, 8x4 per thread.
// =================================================================
__global__ __launch_bounds__(256) void gemm_bias(
    const float* __restrict__ A, const float* __restrict__ W,
    const float* __restrict__ bias, float* __restrict__ C,
    int M, int N, int K)
{
    const int BM = 128, BN = 64, BK = 16;
    __shared__ float As[BK][BM + 1];
    __shared__ float Bs[BK][BN + 1];

    int tid = threadIdx.x;
    int bx = blockIdx.x, by = blockIdx.y;
    int ty = tid >> 4;          // 0..15  (rows)
    int tx = tid & 15;          // 0..15  (cols)

    int ar = tid >> 2;          // 0..63
    int ac4 = (tid & 3) * 4;    // k offset (x4 floats)

    float acc[8][4];
#pragma unroll
    for (int i = 0; i < 8; i++)
#pragma unroll
        for (int j = 0; j < 4; j++) acc[i][j] = 0.f;

    for (int k0 = 0; k0 < K; k0 += BK) {
        float4 a0 = *(const float4*)(A + (size_t)(by * BM + ar) * K + k0 + ac4);
        float4 a1 = *(const float4*)(A + (size_t)(by * BM + ar + 64) * K + k0 + ac4);
        float4 b0 = *(const float4*)(W + (size_t)(bx * BN + ar) * K + k0 + ac4);
        __syncthreads();
        As[ac4 + 0][ar] = a0.x; As[ac4 + 1][ar] = a0.y;
        As[ac4 + 2][ar] = a0.z; As[ac4 + 3][ar] = a0.w;
        As[ac4 + 0][ar + 64] = a1.x; As[ac4 + 1][ar + 64] = a1.y;
        As[ac4 + 2][ar + 64] = a1.z; As[ac4 + 3][ar + 64] = a1.w;
        Bs[ac4 + 0][ar] = b0.x; Bs[ac4 + 1][ar] = b0.y;
        Bs[ac4 + 2][ar] = b0.z; Bs[ac4 + 3][ar] = b0.w;
        __syncthreads();
#pragma unroll
        for (int k = 0; k < BK; k++) {
            float ra[8], rb[4];
#pragma unroll
            for (int i = 0; i < 8; i++) ra[i] = As[k][ty * 8 + i];
#pragma unroll
            for (int j = 0; j < 4; j++) rb[j] = Bs[k][tx * 4 + j];
#pragma unroll
            for (int i = 0; i < 8; i++)
#pragma unroll
                for (int j = 0; j < 4; j++) acc[i][j] = fmaf(ra[i], rb[j], acc[i][j]);
        }
    }

    float4 bv = ((const float4*)bias)[bx * 16 + tx];
#pragma unroll
    for (int i = 0; i < 8; i++) {
        int row = by * BM + ty * 8 + i;
        float4 v;
        v.x = acc[i][0] + bv.x; v.y = acc[i][1] + bv.y;
        v.z = acc[i][2] + bv.z; v.w = acc[i][3] + bv.w;
        ((float4*)(C + (size_t)row * N))[bx * 16 + tx] = v;
    }
}

// =================================================================
// s[i] = h[i,:] . a[0:F],  t[i] = h[i,:] . a[F:2F]
// one warp per row, 8 rows per block
// =================================================================
template <int F>
__global__ __launch_bounds__(256) void st_kernel(
    const float* __restrict__ h, const float* __restrict__ a,
    float* __restrict__ s, float* __restrict__ t)
{
    int warp = threadIdx.x >> 5, lane = threadIdx.x & 31;
    int row = blockIdx.x * 8 + warp;
    const float* hr = h + (size_t)row * F;
    float lo = 0.f, hi = 0.f;
#pragma unroll
    for (int f = lane; f < F; f += 32) {
        float v = hr[f];
        lo = fmaf(v, a[f], lo);
        hi = fmaf(v, a[F + f], hi);
    }
#pragma unroll
    for (int o = 16; o; o >>= 1) {
        lo += __shfl_xor_sync(0xffffffffu, lo, o);
        hi += __shfl_xor_sync(0xffffffffu, hi, o);
    }
    if (lane == 0) { s[row] = lo; t[row] = hi; }
}

// =================================================================
// Fused GAT attention layer (flash-attention style, online softmax):
//   out[i,:] = post( softmax_j( mask(lrelu(s_i + t_j + ab), adj) ) @ h )
// post = elu(elu(.))  (layer 1, written to g_y1)
//      = log_softmax(elu(.)) (layer 2 / FINAL, written to d_out)
// BM=64 rows/block, BJ=32 j per tile, 256 threads.
// =================================================================
template <int NF, bool FINAL>
__global__ __launch_bounds__(256) void attn_kernel(
    const float* __restrict__ hG, const int* __restrict__ adj,
    const float* __restrict__ sG, const float* __restrict__ tG,
    const float* __restrict__ abG, float* __restrict__ outG)
{
    constexpr int BM = 64, BJ = 32;
    constexpr int NF4 = NF / 4;
    constexpr int NTN = NF / 64;    // float4 col-groups per thread (4 or 1)

    __shared__ __align__(16) float hs[BJ * NF];      // h tile
    __shared__ __align__(16) float Ps[BM * BJ];      // probability tile
    __shared__ float sRow[BM], mRow[BM], lRow[BM], aRow[BM];

    const int tid = threadIdx.x;
    const int i0 = blockIdx.x * BM;
    const float ab = abG[0];

    if (tid < BM) {
        sRow[tid] = sG[i0 + tid] + ab;
        mRow[tid] = __int_as_float(0xff800000);      // -inf
        lRow[tid] = 0.f;
    }

    const int ty = tid >> 4, tx = tid & 15;          // phase-C mapping
    const int r = tid >> 2, cg = tid & 3;            // phase-A mapping

    float4 acc[4][NTN];
#pragma unroll
    for (int tm = 0; tm < 4; tm++)
#pragma unroll
        for (int g = 0; g < NTN; g++) acc[tm][g] = make_float4(0.f, 0.f, 0.f, 0.f);

    __syncthreads();

    for (int j0 = 0; j0 < NN; j0 += BJ) {
        // -------- load h tile into smem (hs free: prev phase C done) ------
#pragma unroll
        for (int it = 0; it < (BJ * NF4) / 256; ++it) {
            int id = tid + it * 256;
            int row = id / NF4, c = id % NF4;
            ((float4*)hs)[id] = ((const float4*)(hG + (size_t)(j0 + row) * NF))[c];
        }

        // -------- phase A: scores + online softmax for 8 cols ------------
        const int4* ap = (const int4*)(adj + (size_t)(i0 + r) * NN + j0 + cg * 8);
        int4 A0 = ap[0], A1 = ap[1];
        const float sv = sRow[r];
        const float* tp = tG + j0 + cg * 8;
        float e[8];
        {
            int av[8] = {A0.x, A0.y, A0.z, A0.w, A1.x, A1.y, A1.z, A1.w};
#pragma unroll
            for (int k = 0; k < 8; k++) {
                float ev = sv + tp[k];
                ev = fmaxf(ev, LRELU_A * ev);        // leaky relu
                e[k] = (av[k] > 0) ? ev : NEGV;
            }
        }
        float tmax = e[0];
#pragma unroll
        for (int k = 1; k < 8; k++) tmax = fmaxf(tmax, e[k]);
        tmax = fmaxf(tmax, __shfl_xor_sync(0xffffffffu, tmax, 1));
        tmax = fmaxf(tmax, __shfl_xor_sync(0xffffffffu, tmax, 2));

        float m_old = mRow[r];
        float m_new = fmaxf(m_old, tmax);
        float p[8], ps = 0.f;
#pragma unroll
        for (int k = 0; k < 8; k++) { p[k] = __expf(e[k] - m_new); ps += p[k]; }
        ps += __shfl_xor_sync(0xffffffffu, ps, 1);
        ps += __shfl_xor_sync(0xffffffffu, ps, 2);

        ((float4*)Ps)[r * 8 + cg * 2 + 0] = make_float4(p[0], p[1], p[2], p[3]);
        ((float4*)Ps)[r * 8 + cg * 2 + 1] = make_float4(p[4], p[5], p[6], p[7]);
        if (cg == 0) {
            float al = __expf(m_old - m_new);
            aRow[r] = al;
            lRow[r] = lRow[r] * al + ps;
            mRow[r] = m_new;
        }
        __syncthreads();    // hs, Ps, aRow ready

        // -------- phase C: acc = acc*alpha + P @ h_tile ------------------
#pragma unroll
        for (int tm = 0; tm < 4; tm++) {
            float al = aRow[ty * 4 + tm];
#pragma unroll
            for (int g = 0; g < NTN; g++) {
                acc[tm][g].x *= al; acc[tm][g].y *= al;
                acc[tm][g].z *= al; acc[tm][g].w *= al;
            }
        }
#pragma unroll 8
        for (int k = 0; k < BJ; k++) {
            float4 hv[NTN];
#pragma unroll
            for (int g = 0; g < NTN; g++) hv[g] = ((const float4*)hs)[k * NF4 + g * 16 + tx];
            float pr[4];
#pragma unroll
            for (int tm = 0; tm < 4; tm++) pr[tm] = Ps[(ty * 4 + tm) * BJ + k];
#pragma unroll
            for (int tm = 0; tm < 4; tm++)
#pragma unroll
                for (int g = 0; g < NTN; g++) {
                    acc[tm][g].x = fmaf(pr[tm], hv[g].x, acc[tm][g].x);
                    acc[tm][g].y = fmaf(pr[tm], hv[g].y, acc[tm][g].y);
                    acc[tm][g].z = fmaf(pr[tm], hv[g].z, acc[tm][g].z);
                    acc[tm][g].w = fmaf(pr[tm], hv[g].w, acc[tm][g].w);
                }
        }
        __syncthreads();    // before next iteration overwrites hs/Ps
    }

    // -------- epilogue ---------------------------------------------------
#pragma unroll
    for (int tm = 0; tm < 4; tm++) {
        int rloc = ty * 4 + tm;
        int row = i0 + rloc;
        float inv = 1.f / lRow[rloc];
        if (!FINAL) {
#pragma unroll
            for (int g = 0; g < NTN; g++) {
                float4 v = acc[tm][g];
                v.x = elu1(elu1(v.x * inv)); v.y = elu1(elu1(v.y * inv));
                v.z = elu1(elu1(v.z * inv)); v.w = elu1(elu1(v.w * inv));
                ((float4*)(outG + (size_t)row * NF))[g * 16 + tx] = v;
            }
        } else {
            // NF==64, NTN==1: 16 lanes (same warp half) own the full row
            float4 z = acc[tm][0];
            z.x = elu1(z.x * inv); z.y = elu1(z.y * inv);
            z.z = elu1(z.z * inv); z.w = elu1(z.w * inv);
            float mx = fmaxf(fmaxf(z.x, z.y), fmaxf(z.z, z.w));
#pragma unroll
            for (int o = 1; o < 16; o <<= 1)
                mx = fmaxf(mx, __shfl_xor_sync(0xffffffffu, mx, o));
            float se = expf(z.x - mx) + expf(z.y - mx) + expf(z.z - mx) + expf(z.w - mx);
#pragma unroll
            for (int o = 1; o < 16; o <<= 1)
                se += __shfl_xor_sync(0xffffffffu, se, o);
            float lse = mx + logf(se);
            float4 v = make_float4(z.x - lse, z.y - lse, z.z - lse, z.w - lse);
            ((float4*)(outG + (size_t)row * FOUT))[tx] = v;
        }
    }
}

// =================================================================
extern "C" void kernel_launch(void* const* d_in, const int* in_sizes, int n_in,
                              void* d_out, int out_size)
{
    const float* x   = (const float*)d_in[0];
    const int*   adj = (const int*)  d_in[1];
    const float* W1  = (const float*)d_in[2];
    const float* b1  = (const float*)d_in[3];
    const float* a1  = (const float*)d_in[4];
    const float* ab1 = (const float*)d_in[5];
    const float* W2  = (const float*)d_in[6];
    const float* b2  = (const float*)d_in[7];
    const float* a2  = (const float*)d_in[8];
    const float* ab2 = (const float*)d_in[9];
    float* out = (float*)d_out;

    void *h1p, *y1p, *h2p, *s1p, *t1p, *s2p, *t2p;
    cudaGetSymbolAddress(&h1p, g_h1);
    cudaGetSymbolAddress(&y1p, g_y1);
    cudaGetSymbolAddress(&h2p, g_h2);
    cudaGetSymbolAddress(&s1p, g_s1);
    cudaGetSymbolAddress(&t1p, g_t1);
    cudaGetSymbolAddress(&s2p, g_s2);
    cudaGetSymbolAddress(&t2p, g_t2);
    float* h1 = (float*)h1p; float* y1 = (float*)y1p; float* h2 = (float*)h2p;
    float* s1 = (float*)s1p; float* t1 = (float*)t1p;
    float* s2 = (float*)s2p; float* t2 = (float*)t2p;

    // Layer 1
    gemm_bias<<<dim3(FH / 64, NN / 128), 256>>>(x, W1, b1, h1, NN, FH, FIN);
    st_kernel<FH><<<NN / 8, 256>>>(h1, a1, s1, t1);
    attn_kernel<FH, false><<<NN / 64, 256>>>(h1, adj, s1, t1, ab1, y1);

    // Layer 2
    gemm_bias<<<dim3(FOUT / 64, NN / 128), 256>>>(y1, W2, b2, h2, NN, FOUT, FH);
    st_kernel<FOUT><<<NN / 8, 256>>>(h2, a2, s2, t2);
    attn_kernel<FOUT, true><<<NN / 64, 256>>>(h2, adj, s2, t2, ab2, out);
}

// round 2
// speedup vs baseline: 1.6353x; 1.6353x over previous
#include <cuda_runtime.h>
#include <math.h>
#include <stdint.h>

#define NN 8192
#define FIN 512
#define FH 256
#define FOUT 64
#define LRELU_A 0.2f

// ---------------- scratch (no allocations allowed) ----------------
__device__ float g_h1[NN * FH];
__device__ float g_y1[NN * FH];
__device__ float g_h2[NN * FOUT];
__device__ float g_s1[NN], g_t1[NN];
__device__ float g_s2[NN], g_t2[NN];
__device__ float g_tmax1[1], g_tmax2[1];

__device__ __forceinline__ float elu1(float x) { return x > 0.f ? x : expm1f(x); }

__device__ __forceinline__ uint32_t f2tf32(float x) {
    uint32_t r;
    asm("cvt.rna.tf32.f32 %0, %1;" : "=r"(r) : "f"(x));
    return r;
}

__device__ __forceinline__ void mma1688(float d[4], uint32_t a0, uint32_t a1,
                                        uint32_t a2, uint32_t a3,
                                        uint32_t b0, uint32_t b1) {
    asm volatile(
        "mma.sync.aligned.m16n8k8.row.col.f32.tf32.tf32.f32 "
        "{%0,%1,%2,%3}, {%4,%5,%6,%7}, {%8,%9}, {%0,%1,%2,%3};"
        : "+f"(d[0]), "+f"(d[1]), "+f"(d[2]), "+f"(d[3])
        : "r"(a0), "r"(a1), "r"(a2), "r"(a3), "r"(b0), "r"(b1));
}

// =================================================================
// GEMM: C[M,N] = A[M,K] @ W[N,K]^T + bias[N]  (unchanged, 30us)
// =================================================================
__global__ __launch_bounds__(256) void gemm_bias(
    const float* __restrict__ A, const float* __restrict__ W,
    const float* __restrict__ bias, float* __restrict__ C,
    int M, int N, int K)
{
    const int BM = 128, BN = 64, BK = 16;
    __shared__ float As[BK][BM + 1];
    __shared__ float Bs[BK][BN + 1];

    int tid = threadIdx.x;
    int bx = blockIdx.x, by = blockIdx.y;
    int ty = tid >> 4, tx = tid & 15;
    int ar = tid >> 2, ac4 = (tid & 3) * 4;

    float acc[8][4];
#pragma unroll
    for (int i = 0; i < 8; i++)
#pragma unroll
        for (int j = 0; j < 4; j++) acc[i][j] = 0.f;

    for (int k0 = 0; k0 < K; k0 += BK) {
        float4 a0 = *(const float4*)(A + (size_t)(by * BM + ar) * K + k0 + ac4);
        float4 a1 = *(const float4*)(A + (size_t)(by * BM + ar + 64) * K + k0 + ac4);
        float4 b0 = *(const float4*)(W + (size_t)(bx * BN + ar) * K + k0 + ac4);
        __syncthreads();
        As[ac4 + 0][ar] = a0.x; As[ac4 + 1][ar] = a0.y;
        As[ac4 + 2][ar] = a0.z; As[ac4 + 3][ar] = a0.w;
        As[ac4 + 0][ar + 64] = a1.x; As[ac4 + 1][ar + 64] = a1.y;
        As[ac4 + 2][ar + 64] = a1.z; As[ac4 + 3][ar + 64] = a1.w;
        Bs[ac4 + 0][ar] = b0.x; Bs[ac4 + 1][ar] = b0.y;
        Bs[ac4 + 2][ar] = b0.z; Bs[ac4 + 3][ar] = b0.w;
        __syncthreads();
#pragma unroll
        for (int k = 0; k < BK; k++) {
            float ra[8], rb[4];
#pragma unroll
            for (int i = 0; i < 8; i++) ra[i] = As[k][ty * 8 + i];
#pragma unroll
            for (int j = 0; j < 4; j++) rb[j] = Bs[k][tx * 4 + j];
#pragma unroll
            for (int i = 0; i < 8; i++)
#pragma unroll
                for (int j = 0; j < 4; j++) acc[i][j] = fmaf(ra[i], rb[j], acc[i][j]);
        }
    }

    float4 bv = ((const float4*)bias)[bx * 16 + tx];
#pragma unroll
    for (int i = 0; i < 8; i++) {
        int row = by * BM + ty * 8 + i;
        float4 v;
        v.x = acc[i][0] + bv.x; v.y = acc[i][1] + bv.y;
        v.z = acc[i][2] + bv.z; v.w = acc[i][3] + bv.w;
        ((float4*)(C + (size_t)row * N))[bx * 16 + tx] = v;
    }
}

// =================================================================
// s/t projections: one warp per row
// =================================================================
template <int F>
__global__ __launch_bounds__(256) void st_kernel(
    const float* __restrict__ h, const float* __restrict__ a,
    float* __restrict__ s, float* __restrict__ t)
{
    int warp = threadIdx.x >> 5, lane = threadIdx.x & 31;
    int row = blockIdx.x * 8 + warp;
    const float* hr = h + (size_t)row * F;
    float lo = 0.f, hi = 0.f;
#pragma unroll
    for (int f = lane; f < F; f += 32) {
        float v = hr[f];
        lo = fmaf(v, a[f], lo);
        hi = fmaf(v, a[F + f], hi);
    }
#pragma unroll
    for (int o = 16; o; o >>= 1) {
        lo += __shfl_xor_sync(0xffffffffu, lo, o);
        hi += __shfl_xor_sync(0xffffffffu, hi, o);
    }
    if (lane == 0) { s[row] = lo; t[row] = hi; }
}

// global max of t (8192 elems), single block
__global__ __launch_bounds__(256) void max_reduce(const float* __restrict__ t,
                                                  float* __restrict__ out)
{
    __shared__ float sm[256];
    float m = -INFINITY;
    for (int i = threadIdx.x; i < NN; i += 256) m = fmaxf(m, t[i]);
    sm[threadIdx.x] = m;
    __syncthreads();
    for (int o = 128; o; o >>= 1) {
        if (threadIdx.x < o) sm[threadIdx.x] = fmaxf(sm[threadIdx.x], sm[threadIdx.x + o]);
        __syncthreads();
    }
    if (threadIdx.x == 0) out[0] = sm[0];
}

// =================================================================
// Fused GAT attention with tf32 mma.sync (fixed safe-max softmax):
//   out[i,:] = post( (1/l_i) * sum_j exp(e_ij - M_i) * h[j,:] )
//   e_ij = lrelu(s_i + t_j + ab) masked;  M_i = lrelu(s_i + ab + max t)
// BM=64, BJ=32, 256 threads (8 warps: 4 row-groups x 2 col-halves).
// =================================================================
template <int NF, bool FINAL>
__global__ __launch_bounds__(256, 1) void attn_mma(
    const float* __restrict__ hG, const int* __restrict__ adj,
    const float* __restrict__ sG, const float* __restrict__ tG,
    const float* __restrict__ abG, const float* __restrict__ tmaxG,
    float* __restrict__ outG)
{
    constexpr int CTN = NF / 8;    // global 8-col tiles
    constexpr int NCT = NF / 16;   // 8-col tiles per warp (col-half)
    constexpr int GPW = CTN / 2;   // Bf (k,ct) groups per warp

    // B fragments: Bf[k][ct][lane] = {H[8k+tig][8ct+g], H[8k+4+tig][8ct+g]} (tf32)
    __shared__ float2 Bf[4][CTN][32];
    // A fragments: Pf[k][row][tig] = {P[row][8k+tig], P[row][8k+tig+4]} (tf32)
    __shared__ float2 Pf[4][64][4];
    __shared__ float lRow[64];
    __shared__ float zs[FINAL ? 64 * 68 : 1];

    const int tid = threadIdx.x;
    const int w = tid >> 5, lane = tid & 31;
    const int g = lane >> 2, tig = lane & 3;
    const int wr = w >> 1, wc = w & 1;
    const int R0 = wr * 16, C0 = wc * (NF / 2);
    const int i0 = blockIdx.x * 64;

    // phase-A mapping: thread (ar, acg) handles row ar, cols 8*acg..8*acg+7
    const int ar = tid >> 2, acg = tid & 3;
    const float sv = sG[i0 + ar] + abG[0];
    const float Ma = sv + tmaxG[0];
    const float M = fmaxf(Ma, LRELU_A * Ma);
    float lacc = 0.f;

    float acc[NCT][4];
#pragma unroll
    for (int c = 0; c < NCT; c++)
#pragma unroll
        for (int q = 0; q < 4; q++) acc[c][q] = 0.f;

    const int* arow = adj + (size_t)(i0 + ar) * NN;

    // ---- prefetch tile 0 ----
    int4 A0 = ((const int4*)(arow + acg * 8))[0];
    int4 A1 = ((const int4*)(arow + acg * 8))[1];
    float hp0[GPW], hp1[GPW];
#pragma unroll
    for (int gi = 0; gi < GPW; gi++) {
        int ggi = w * GPW + gi;
        int k = ggi / CTN, ct = ggi % CTN;
        int row0 = 8 * k + tig, col = 8 * ct + g;
        hp0[gi] = hG[(size_t)row0 * NF + col];
        hp1[gi] = hG[(size_t)(row0 + 4) * NF + col];
    }

    for (int j0 = 0; j0 < NN; j0 += 32) {
        __syncthreads();   // Bf/Pf free (previous mma done)

        // ---- stage H tile into frag layout ----
#pragma unroll
        for (int gi = 0; gi < GPW; gi++) {
            int ggi = w * GPW + gi;
            int k = ggi / CTN, ct = ggi % CTN;
            Bf[k][ct][lane] = make_float2(__uint_as_float(f2tf32(hp0[gi])),
                                          __uint_as_float(f2tf32(hp1[gi])));
        }

        // ---- phase A: masked exp scores into Pf ----
        float4 t0 = ((const float4*)(tG + j0 + acg * 8))[0];
        float4 t1 = ((const float4*)(tG + j0 + acg * 8))[1];
        float tv[8] = {t0.x, t0.y, t0.z, t0.w, t1.x, t1.y, t1.z, t1.w};
        int av[8] = {A0.x, A0.y, A0.z, A0.w, A1.x, A1.y, A1.z, A1.w};
        float p[8];
#pragma unroll
        for (int k2 = 0; k2 < 8; k2++) {
            float e = sv + tv[k2];
            e = fmaxf(e, LRELU_A * e);
            p[k2] = (av[k2] > 0) ? __expf(e - M) : 0.f;
            lacc += p[k2];
        }
        float4* pfr = (float4*)&Pf[acg][ar][0];
        pfr[0] = make_float4(__uint_as_float(f2tf32(p[0])), __uint_as_float(f2tf32(p[4])),
                             __uint_as_float(f2tf32(p[1])), __uint_as_float(f2tf32(p[5])));
        pfr[1] = make_float4(__uint_as_float(f2tf32(p[2])), __uint_as_float(f2tf32(p[6])),
                             __uint_as_float(f2tf32(p[3])), __uint_as_float(f2tf32(p[7])));

        // ---- prefetch next tile (hidden under mma) ----
        int j0n = j0 + 32;
        if (j0n < NN) {
            A0 = ((const int4*)(arow + j0n + acg * 8))[0];
            A1 = ((const int4*)(arow + j0n + acg * 8))[1];
#pragma unroll
            for (int gi = 0; gi < GPW; gi++) {
                int ggi = w * GPW + gi;
                int k = ggi / CTN, ct = ggi % CTN;
                int row0 = 8 * k + tig, col = 8 * ct + g;
                hp0[gi] = hG[(size_t)(j0n + row0) * NF + col];
                hp1[gi] = hG[(size_t)(j0n + row0 + 4) * NF + col];
            }
        }

        __syncthreads();   // Bf/Pf ready

        // ---- mma phase: acc += P @ H ----
#pragma unroll
        for (int k = 0; k < 4; k++) {
            float2 a01 = Pf[k][R0 + g][tig];
            float2 a11 = Pf[k][R0 + 8 + g][tig];
            uint32_t a0 = __float_as_uint(a01.x), a2 = __float_as_uint(a01.y);
            uint32_t a1 = __float_as_uint(a11.x), a3 = __float_as_uint(a11.y);
#pragma unroll
            for (int ct = 0; ct < NCT; ct++) {
                float2 b = Bf[k][wc * NCT + ct][lane];
                mma1688(acc[ct], a0, a1, a2, a3,
                        __float_as_uint(b.x), __float_as_uint(b.y));
            }
        }
    }

    // ---- softmax denominators ----
    lacc += __shfl_xor_sync(0xffffffffu, lacc, 1);
    lacc += __shfl_xor_sync(0xffffffffu, lacc, 2);
    if (acg == 0) lRow[ar] = lacc;
    __syncthreads();

    const int r0 = R0 + g, r1 = R0 + 8 + g;
    const float inv0 = 1.f / lRow[r0];
    const float inv1 = 1.f / lRow[r1];

    if (!FINAL) {
#pragma unroll
        for (int ct = 0; ct < NCT; ct++) {
            int c = C0 + 8 * ct + 2 * tig;
            float2 v0 = make_float2(elu1(elu1(acc[ct][0] * inv0)),
                                    elu1(elu1(acc[ct][1] * inv0)));
            float2 v1 = make_float2(elu1(elu1(acc[ct][2] * inv1)),
                                    elu1(elu1(acc[ct][3] * inv1)));
            *(float2*)(outG + (size_t)(i0 + r0) * NF + c) = v0;
            *(float2*)(outG + (size_t)(i0 + r1) * NF + c) = v1;
        }
    } else {
        // elu -> smem -> per-row log_softmax over 64 cols
#pragma unroll
        for (int ct = 0; ct < NCT; ct++) {
            int c = C0 + 8 * ct + 2 * tig;
            *(float2*)&zs[r0 * 68 + c] = make_float2(elu1(acc[ct][0] * inv0),
                                                     elu1(acc[ct][1] * inv0));
            *(float2*)&zs[r1 * 68 + c] = make_float2(elu1(acc[ct][2] * inv1),
                                                     elu1(acc[ct][3] * inv1));
        }
        __syncthreads();
        int qr = tid >> 2, ql = tid & 3;
        float z[16];
#pragma unroll
        for (int i = 0; i < 4; i++) {
            float4 v = *(float4*)&zs[qr * 68 + ql * 16 + 4 * i];
            z[4 * i] = v.x; z[4 * i + 1] = v.y; z[4 * i + 2] = v.z; z[4 * i + 3] = v.w;
        }
        float mx = z[0];
#pragma unroll
        for (int i = 1; i < 16; i++) mx = fmaxf(mx, z[i]);
        mx = fmaxf(mx, __shfl_xor_sync(0xffffffffu, mx, 1));
        mx = fmaxf(mx, __shfl_xor_sync(0xffffffffu, mx, 2));
        float se = 0.f;
#pragma unroll
        for (int i = 0; i < 16; i++) se += __expf(z[i] - mx);
        se += __shfl_xor_sync(0xffffffffu, se, 1);
        se += __shfl_xor_sync(0xffffffffu, se, 2);
        float lse = mx + logf(se);
#pragma unroll
        for (int i = 0; i < 4; i++) {
            float4 o = make_float4(z[4 * i] - lse, z[4 * i + 1] - lse,
                                   z[4 * i + 2] - lse, z[4 * i + 3] - lse);
            *(float4*)(outG + (size_t)(i0 + qr) * FOUT + ql * 16 + 4 * i) = o;
        }
    }
}

// =================================================================
extern "C" void kernel_launch(void* const* d_in, const int* in_sizes, int n_in,
                              void* d_out, int out_size)
{
    const float* x   = (const float*)d_in[0];
    const int*   adj = (const int*)  d_in[1];
    const float* W1  = (const float*)d_in[2];
    const float* b1  = (const float*)d_in[3];
    const float* a1  = (const float*)d_in[4];
    const float* ab1 = (const float*)d_in[5];
    const float* W2  = (const float*)d_in[6];
    const float* b2  = (const float*)d_in[7];
    const float* a2  = (const float*)d_in[8];
    const float* ab2 = (const float*)d_in[9];
    float* out = (float*)d_out;

    void *h1p, *y1p, *h2p, *s1p, *t1p, *s2p, *t2p, *m1p, *m2p;
    cudaGetSymbolAddress(&h1p, g_h1);
    cudaGetSymbolAddress(&y1p, g_y1);
    cudaGetSymbolAddress(&h2p, g_h2);
    cudaGetSymbolAddress(&s1p, g_s1);
    cudaGetSymbolAddress(&t1p, g_t1);
    cudaGetSymbolAddress(&s2p, g_s2);
    cudaGetSymbolAddress(&t2p, g_t2);
    cudaGetSymbolAddress(&m1p, g_tmax1);
    cudaGetSymbolAddress(&m2p, g_tmax2);
    float* h1 = (float*)h1p; float* y1 = (float*)y1p; float* h2 = (float*)h2p;
    float* s1 = (float*)s1p; float* t1 = (float*)t1p;
    float* s2 = (float*)s2p; float* t2 = (float*)t2p;
    float* m1 = (float*)m1p; float* m2 = (float*)m2p;

    // Layer 1
    gemm_bias<<<dim3(FH / 64, NN / 128), 256>>>(x, W1, b1, h1, NN, FH, FIN);
    st_kernel<FH><<<NN / 8, 256>>>(h1, a1, s1, t1);
    max_reduce<<<1, 256>>>(t1, m1);
    attn_mma<FH, false><<<NN / 64, 256>>>(h1, adj, s1, t1, ab1, m1, y1);

    // Layer 2
    gemm_bias<<<dim3(FOUT / 64, NN / 128), 256>>>(y1, W2, b2, h2, NN, FOUT, FH);
    st_kernel<FOUT><<<NN / 8, 256>>>(h2, a2, s2, t2);
    max_reduce<<<1, 256>>>(t2, m2);
    attn_mma<FOUT, true><<<NN / 64, 256>>>(h2, adj, s2, t2, ab2, m2, out);
}

// round 5
// speedup vs baseline: 2.4186x; 1.4791x over previous
#include <cuda_runtime.h>
#include <cuda_fp16.h>
#include <math.h>
#include <stdint.h>

#define NN 8192
#define FIN 512
#define FH 256
#define FOUT 64
#define LRELU_A 0.2f

// ---------------- scratch (no allocations allowed) ----------------
__device__ float g_h1[NN * FH];
__device__ float g_y1[NN * FH];
__device__ float g_h2[NN * FOUT];
__device__ __half g_h1T[FH * NN];     // transposed fp16 h1
__device__ __half g_h2T[FOUT * NN];   // transposed fp16 h2
__device__ float g_s1[NN], g_t1[NN];
__device__ float g_s2[NN], g_t2[NN];
__device__ float g_tmax1[1], g_tmax2[1];

__device__ __forceinline__ float elu1(float x) { return x > 0.f ? x : expm1f(x); }

__device__ __forceinline__ void ldsm4(uint32_t& r0, uint32_t& r1, uint32_t& r2,
                                      uint32_t& r3, uint32_t addr) {
    asm volatile("ldmatrix.sync.aligned.m8n8.x4.shared.b16 {%0,%1,%2,%3}, [%4];"
                 : "=r"(r0), "=r"(r1), "=r"(r2), "=r"(r3) : "r"(addr));
}

__device__ __forceinline__ void mma16816(float d[4], uint32_t a0, uint32_t a1,
                                         uint32_t a2, uint32_t a3,
                                         uint32_t b0, uint32_t b1) {
    asm volatile(
        "mma.sync.aligned.m16n8k16.row.col.f32.f16.f16.f32 "
        "{%0,%1,%2,%3}, {%4,%5,%6,%7}, {%8,%9}, {%0,%1,%2,%3};"
        : "+f"(d[0]), "+f"(d[1]), "+f"(d[2]), "+f"(d[3])
        : "r"(a0), "r"(a1), "r"(a2), "r"(a3), "r"(b0), "r"(b1));
}

__device__ __forceinline__ void cp16(uint32_t dst, const void* src) {
    asm volatile("cp.async.cg.shared.global [%0], [%1], 16;" :: "r"(dst), "l"(src));
}

// =================================================================
// GEMM: C[M,N] = A[M,K] @ W[N,K]^T + bias[N]
// =================================================================
__global__ __launch_bounds__(256) void gemm_bias(
    const float* __restrict__ A, const float* __restrict__ W,
    const float* __restrict__ bias, float* __restrict__ C,
    int M, int N, int K)
{
    const int BM = 128, BN = 64, BK = 16;
    __shared__ float As[BK][BM + 1];
    __shared__ float Bs[BK][BN + 1];

    int tid = threadIdx.x;
    int bx = blockIdx.x, by = blockIdx.y;
    int ty = tid >> 4, tx = tid & 15;
    int ar = tid >> 2, ac4 = (tid & 3) * 4;

    float acc[8][4];
#pragma unroll
    for (int i = 0; i < 8; i++)
#pragma unroll
        for (int j = 0; j < 4; j++) acc[i][j] = 0.f;

    for (int k0 = 0; k0 < K; k0 += BK) {
        float4 a0 = *(const float4*)(A + (size_t)(by * BM + ar) * K + k0 + ac4);
        float4 a1 = *(const float4*)(A + (size_t)(by * BM + ar + 64) * K + k0 + ac4);
        float4 b0 = *(const float4*)(W + (size_t)(bx * BN + ar) * K + k0 + ac4);
        __syncthreads();
        As[ac4 + 0][ar] = a0.x; As[ac4 + 1][ar] = a0.y;
        As[ac4 + 2][ar] = a0.z; As[ac4 + 3][ar] = a0.w;
        As[ac4 + 0][ar + 64] = a1.x; As[ac4 + 1][ar + 64] = a1.y;
        As[ac4 + 2][ar + 64] = a1.z; As[ac4 + 3][ar + 64] = a1.w;
        Bs[ac4 + 0][ar] = b0.x; Bs[ac4 + 1][ar] = b0.y;
        Bs[ac4 + 2][ar] = b0.z; Bs[ac4 + 3][ar] = b0.w;
        __syncthreads();
#pragma unroll
        for (int k = 0; k < BK; k++) {
            float ra[8], rb[4];
#pragma unroll
            for (int i = 0; i < 8; i++) ra[i] = As[k][ty * 8 + i];
#pragma unroll
            for (int j = 0; j < 4; j++) rb[j] = Bs[k][tx * 4 + j];
#pragma unroll
            for (int i = 0; i < 8; i++)
#pragma unroll
                for (int j = 0; j < 4; j++) acc[i][j] = fmaf(ra[i], rb[j], acc[i][j]);
        }
    }

    float4 bv = ((const float4*)bias)[bx * 16 + tx];
#pragma unroll
    for (int i = 0; i < 8; i++) {
        int row = by * BM + ty * 8 + i;
        float4 v;
        v.x = acc[i][0] + bv.x; v.y = acc[i][1] + bv.y;
        v.z = acc[i][2] + bv.z; v.w = acc[i][3] + bv.w;
        ((float4*)(C + (size_t)row * N))[bx * 16 + tx] = v;
    }
}

// =================================================================
// transpose + fp16 convert: h[N][F] float -> hT[F][N] half
// =================================================================
__global__ __launch_bounds__(256) void transpose_half(
    const float* __restrict__ h, __half* __restrict__ hT, int F)
{
    __shared__ float ts[32][33];
    int n0 = blockIdx.x * 32, c0 = blockIdx.y * 32;
    int r = threadIdx.x >> 3, cc = (threadIdx.x & 7) * 4;

    float4 v = *(const float4*)(h + (size_t)(n0 + r) * F + c0 + cc);
    ts[r][cc + 0] = v.x; ts[r][cc + 1] = v.y;
    ts[r][cc + 2] = v.z; ts[r][cc + 3] = v.w;
    __syncthreads();

    int c = threadIdx.x >> 3, nn = (threadIdx.x & 7) * 4;
    __half2 p0 = __floats2half2_rn(ts[nn + 0][c], ts[nn + 1][c]);
    __half2 p1 = __floats2half2_rn(ts[nn + 2][c], ts[nn + 3][c]);
    union { __half2 h2[2]; uint2 u; } cv;
    cv.h2[0] = p0; cv.h2[1] = p1;
    *(uint2*)(hT + (size_t)(c0 + c) * NN + n0 + nn) = cv.u;
}

// =================================================================
// s/t projections: one warp per row
// =================================================================
template <int F>
__global__ __launch_bounds__(256) void st_kernel(
    const float* __restrict__ h, const float* __restrict__ a,
    float* __restrict__ s, float* __restrict__ t)
{
    int warp = threadIdx.x >> 5, lane = threadIdx.x & 31;
    int row = blockIdx.x * 8 + warp;
    const float* hr = h + (size_t)row * F;
    float lo = 0.f, hi = 0.f;
#pragma unroll
    for (int f = lane; f < F; f += 32) {
        float v = hr[f];
        lo = fmaf(v, a[f], lo);
        hi = fmaf(v, a[F + f], hi);
    }
#pragma unroll
    for (int o = 16; o; o >>= 1) {
        lo += __shfl_xor_sync(0xffffffffu, lo, o);
        hi += __shfl_xor_sync(0xffffffffu, hi, o);
    }
    if (lane == 0) { s[row] = lo; t[row] = hi; }
}

__global__ __launch_bounds__(256) void max_reduce(const float* __restrict__ t,
                                                  float* __restrict__ out)
{
    __shared__ float sm[256];
    float m = -INFINITY;
    for (int i = threadIdx.x; i < NN; i += 256) m = fmaxf(m, t[i]);
    sm[threadIdx.x] = m;
    __syncthreads();
    for (int o = 128; o; o >>= 1) {
        if (threadIdx.x < o) sm[threadIdx.x] = fmaxf(sm[threadIdx.x], sm[threadIdx.x + o]);
        __syncthreads();
    }
    if (threadIdx.x == 0) out[0] = sm[0];
}

// =================================================================
// Fused GAT attention, fp16 mma + cp.async + ldmatrix, BJ=64 double-buffered.
// Dynamic smem: [Ht0][Ht1][Ps0][Ps1][lRow]
//   Ht: NF rows x 128B (64 fp16 j-values per row), 16B xor-swizzled
//   Ps: 64 rows x 128B (64 fp16 probs per row), 16B xor-swizzled
// 8 warps: warp (wr, wc) owns rows [16*wr,16*wr+16) x cols [wc*NF/2, ...)
// =================================================================
template <int NF, bool FINAL>
__global__ __launch_bounds__(256) void attn_mma(
    const __half* __restrict__ hTg, const int* __restrict__ adj,
    const float* __restrict__ sG, const float* __restrict__ tG,
    const float* __restrict__ abG, const float* __restrict__ tmaxG,
    float* __restrict__ outG)
{
    constexpr int HTB = NF * 128;              // bytes per Ht buffer
    constexpr int PSB = 64 * 128;              // bytes per Ps buffer
    constexpr int LOFF = 2 * HTB + 2 * PSB;
    constexpr int NCT = NF / 16;               // 8-col mma tiles per warp
    constexpr int NQ = NCT / 2;                // ldmatrix.x4 B loads per k-step
    constexpr int PER = NF * 8 / 256;          // cp.async chunks per thread
    constexpr int NT = NN / 64;

    extern __shared__ char smem[];
    const uint32_t sb = (uint32_t)__cvta_generic_to_shared(smem);
    float* lRow = (float*)(smem + LOFF);

    const int tid = threadIdx.x;
    const int lane = tid & 31, w = tid >> 5;
    const int g = lane >> 2, tig = lane & 3;
    const int wr = w >> 1, wc = w & 1;
    const int R0 = wr * 16, C0 = wc * (NF / 2);
    const int i0 = blockIdx.x * 64;

    // phase-A mapping: thread (ar, acg) handles row ar, cols 16*acg..16*acg+15
    const int ar = tid >> 2, acg = tid & 3;
    const float sv = sG[i0 + ar] + abG[0];
    const float Ma = sv + tmaxG[0];
    const float M = fmaxf(Ma, LRELU_A * Ma);
    float lacc = 0.f;

    float acc[NCT][4];
#pragma unroll
    for (int c = 0; c < NCT; c++)
#pragma unroll
        for (int q = 0; q < 4; q++) acc[c][q] = 0.f;

    const int* arow = adj + (size_t)(i0 + ar) * NN;
    const uint32_t xr = (uint32_t)((ar & 7) << 4);          // phase-A write swizzle
    const uint32_t xO = (uint32_t)((lane & 7) << 4);        // ldmatrix row swizzle
    const int aRowB = R0 + (lane & 7) + ((lane >> 3) & 1) * 8;
    const uint32_t aBoff = (uint32_t)((lane >> 4) << 4);
    const int bColB = (lane & 7) + ((lane >> 4) << 3);
    const uint32_t bBoff = (uint32_t)(((lane >> 3) & 1) << 4);

    int4 aj[4];
    float4 tv[4];

#define ISSUE_CP(J0, BUF) do {                                                 \
    uint32_t hb = sb + (BUF) * HTB;                                            \
    _Pragma("unroll")                                                          \
    for (int u = 0; u < PER; u++) {                                            \
        int ci = tid * PER + u;                                                \
        int rr = ci >> 3, ch = ci & 7;                                         \
        uint32_t dst = hb + rr * 128 +                                         \
                       (((uint32_t)(ch * 16)) ^ (((uint32_t)(rr & 7)) << 4));  \
        cp16(dst, hTg + (size_t)rr * NN + (J0) + ch * 8);                      \
    }                                                                          \
    asm volatile("cp.async.commit_group;" ::: "memory");                       \
} while (0)

#define LOAD_AT(J0) do {                                                       \
    _Pragma("unroll")                                                          \
    for (int q = 0; q < 4; q++) {                                              \
        aj[q] = ((const int4*)(arow + (J0) + acg * 16))[q];                    \
        tv[q] = ((const float4*)(tG + (J0) + acg * 16))[q];                    \
    }                                                                          \
} while (0)

#define PHASE_A(BUF) do {                                                      \
    float p[16];                                                               \
    _Pragma("unroll")                                                          \
    for (int q = 0; q < 4; q++) {                                              \
        const int* av = (const int*)&aj[q];                                    \
        const float* tf = (const float*)&tv[q];                                \
        _Pragma("unroll")                                                      \
        for (int m2 = 0; m2 < 4; m2++) {                                       \
            float e = sv + tf[m2];                                             \
            e = fmaxf(e, LRELU_A * e);                                         \
            float pv = (av[m2] > 0) ? __expf(e - M) : 0.f;                     \
            p[q * 4 + m2] = pv; lacc += pv;                                    \
        }                                                                      \
    }                                                                          \
    union { __half2 h2[8]; uint4 u[2]; } cvv;                                  \
    _Pragma("unroll")                                                          \
    for (int m2 = 0; m2 < 8; m2++)                                             \
        cvv.h2[m2] = __floats2half2_rn(p[2 * m2], p[2 * m2 + 1]);              \
    char* pbase = smem + 2 * HTB + (BUF) * PSB + ar * 128;                     \
    *(uint4*)(pbase + (((uint32_t)(acg * 32)) ^ xr)) = cvv.u[0];               \
    *(uint4*)(pbase + (((uint32_t)(acg * 32 + 16)) ^ xr)) = cvv.u[1];          \
} while (0)

    // ---- prologue: tile 0 ----
    ISSUE_CP(0, 0);
    LOAD_AT(0);
    PHASE_A(0);

    for (int i = 0; i < NT; i++) {
        __syncthreads();                       // Ps(i) written; mma(i-1) done
        asm volatile("cp.async.wait_group 0;" ::: "memory");
        __syncthreads();                       // Ht(i) visible to all warps

        const int cb = i & 1, nb = (i + 1) & 1;
        if (i + 1 < NT) {
            ISSUE_CP((i + 1) * 64, nb);
            LOAD_AT((i + 1) * 64);
        }

        // ---- mma(i): acc += P_tile @ H_tile ----
        const uint32_t psA = sb + 2 * HTB + cb * PSB + (uint32_t)aRowB * 128;
        const uint32_t htB = sb + cb * HTB;
#pragma unroll
        for (int k = 0; k < 4; k++) {
            uint32_t a0, a1, a2, a3;
            ldsm4(a0, a1, a2, a3, psA + ((((uint32_t)(32 * k)) + aBoff) ^ xO));
#pragma unroll
            for (int q = 0; q < NQ; q++) {
                uint32_t b0, b1, b2, b3;
                int c = C0 + 16 * q + bColB;
                ldsm4(b0, b1, b2, b3,
                      htB + (uint32_t)c * 128 + ((((uint32_t)(32 * k)) + bBoff) ^ xO));
                mma16816(acc[2 * q + 0], a0, a1, a2, a3, b0, b1);
                mma16816(acc[2 * q + 1], a0, a1, a2, a3, b2, b3);
            }
        }

        if (i + 1 < NT) PHASE_A(nb);
    }

    // ---- softmax denominators ----
    lacc += __shfl_xor_sync(0xffffffffu, lacc, 1);
    lacc += __shfl_xor_sync(0xffffffffu, lacc, 2);
    if (acg == 0) lRow[ar] = lacc;
    __syncthreads();

    const int r0 = R0 + g, r1 = R0 + 8 + g;
    const float inv0 = 1.f / lRow[r0];
    const float inv1 = 1.f / lRow[r1];

    if (!FINAL) {
#pragma unroll
        for (int ct = 0; ct < NCT; ct++) {
            int c = C0 + 8 * ct + 2 * tig;
            float2 v0 = make_float2(elu1(elu1(acc[ct][0] * inv0)),
                                    elu1(elu1(acc[ct][1] * inv0)));
            float2 v1 = make_float2(elu1(elu1(acc[ct][2] * inv1)),
                                    elu1(elu1(acc[ct][3] * inv1)));
            *(float2*)(outG + (size_t)(i0 + r0) * NF + c) = v0;
            *(float2*)(outG + (size_t)(i0 + r1) * NF + c) = v1;
        }
    } else {
        float* zs = (float*)smem;    // reuse Ht/Ps buffers (mma finished)
#pragma unroll
        for (int ct = 0; ct < NCT; ct++) {
            int c = C0 + 8 * ct + 2 * tig;
            *(float2*)&zs[r0 * 68 + c] = make_float2(elu1(acc[ct][0] * inv0),
                                                     elu1(acc[ct][1] * inv0));
            *(float2*)&zs[r1 * 68 + c] = make_float2(elu1(acc[ct][2] * inv1),
                                                     elu1(acc[ct][3] * inv1));
        }
        __syncthreads();
        int qr = tid >> 2, ql = tid & 3;
        float z[16];
#pragma unroll
        for (int i2 = 0; i2 < 4; i2++) {
            float4 v = *(float4*)&zs[qr * 68 + ql * 16 + 4 * i2];
            z[4 * i2] = v.x; z[4 * i2 + 1] = v.y;
            z[4 * i2 + 2] = v.z; z[4 * i2 + 3] = v.w;
        }
        float mx = z[0];
#pragma unroll
        for (int i2 = 1; i2 < 16; i2++) mx = fmaxf(mx, z[i2]);
        mx = fmaxf(mx, __shfl_xor_sync(0xffffffffu, mx, 1));
        mx = fmaxf(mx, __shfl_xor_sync(0xffffffffu, mx, 2));
        float se = 0.f;
#pragma unroll
        for (int i2 = 0; i2 < 16; i2++) se += __expf(z[i2] - mx);
        se += __shfl_xor_sync(0xffffffffu, se, 1);
        se += __shfl_xor_sync(0xffffffffu, se, 2);
        float lse = mx + logf(se);
#pragma unroll
        for (int i2 = 0; i2 < 4; i2++) {
            float4 o = make_float4(z[4 * i2] - lse, z[4 * i2 + 1] - lse,
                                   z[4 * i2 + 2] - lse, z[4 * i2 + 3] - lse);
            *(float4*)(outG + (size_t)(i0 + qr) * FOUT + ql * 16 + 4 * i2) = o;
        }
    }
#undef ISSUE_CP
#undef LOAD_AT
#undef PHASE_A
}

// =================================================================
extern "C" void kernel_launch(void* const* d_in, const int* in_sizes, int n_in,
                              void* d_out, int out_size)
{
    const float* x   = (const float*)d_in[0];
    const int*   adj = (const int*)  d_in[1];
    const float* W1  = (const float*)d_in[2];
    const float* b1  = (const float*)d_in[3];
    const float* a1  = (const float*)d_in[4];
    const float* ab1 = (const float*)d_in[5];
    const float* W2  = (const float*)d_in[6];
    const float* b2  = (const float*)d_in[7];
    const float* a2  = (const float*)d_in[8];
    const float* ab2 = (const float*)d_in[9];
    float* out = (float*)d_out;

    void *h1p, *y1p, *h2p, *h1tp, *h2tp, *s1p, *t1p, *s2p, *t2p, *m1p, *m2p;
    cudaGetSymbolAddress(&h1p, g_h1);
    cudaGetSymbolAddress(&y1p, g_y1);
    cudaGetSymbolAddress(&h2p, g_h2);
    cudaGetSymbolAddress(&h1tp, g_h1T);
    cudaGetSymbolAddress(&h2tp, g_h2T);
    cudaGetSymbolAddress(&s1p, g_s1);
    cudaGetSymbolAddress(&t1p, g_t1);
    cudaGetSymbolAddress(&s2p, g_s2);
    cudaGetSymbolAddress(&t2p, g_t2);
    cudaGetSymbolAddress(&m1p, g_tmax1);
    cudaGetSymbolAddress(&m2p, g_tmax2);
    float* h1 = (float*)h1p; float* y1 = (float*)y1p; float* h2 = (float*)h2p;
    __half* h1T = (__half*)h1tp; __half* h2T = (__half*)h2tp;
    float* s1 = (float*)s1p; float* t1 = (float*)t1p;
    float* s2 = (float*)s2p; float* t2 = (float*)t2p;
    float* m1 = (float*)m1p; float* m2 = (float*)m2p;

    const int SM1 = 2 * (FH * 128) + 2 * 8192 + 256;    // 82176 bytes
    const int SM2 = 2 * (FOUT * 128) + 2 * 8192 + 256;  // 33024 bytes
    cudaFuncSetAttribute(attn_mma<FH, false>,
                         cudaFuncAttributeMaxDynamicSharedMemorySize, SM1);
    cudaFuncSetAttribute(attn_mma<FOUT, true>,
                         cudaFuncAttributeMaxDynamicSharedMemorySize, SM2);

    // Layer 1
    gemm_bias<<<dim3(FH / 64, NN / 128), 256>>>(x, W1, b1, h1, NN, FH, FIN);
    transpose_half<<<dim3(NN / 32, FH / 32), 256>>>(h1, h1T, FH);
    st_kernel<FH><<<NN / 8, 256>>>(h1, a1, s1, t1);
    max_reduce<<<1, 256>>>(t1, m1);
    attn_mma<FH, false><<<NN / 64, 256, SM1>>>(h1T, adj, s1, t1, ab1, m1, y1);

    // Layer 2
    gemm_bias<<<dim3(FOUT / 64, NN / 128), 256>>>(y1, W2, b2, h2, NN, FOUT, FH);
    transpose_half<<<dim3(NN / 32, FOUT / 32), 256>>>(h2, h2T, FOUT);
    st_kernel<FOUT><<<NN / 8, 256>>>(h2, a2, s2, t2);
    max_reduce<<<1, 256>>>(t2, m2);
    attn_mma<FOUT, true><<<NN / 64, 256, SM2>>>(h2T, adj, s2, t2, ab2, m2, out);
}

// round 8
// speedup vs baseline: 2.4290x; 1.0043x over previous
#include <cuda_runtime.h>
#include <cuda_fp16.h>
#include <math.h>
#include <stdint.h>

#define NN 8192
#define FIN 512
#define FH 256
#define FOUT 64
#define LRELU_A 0.2f

// ---------------- scratch (no allocations allowed) ----------------
__device__ float g_h1[NN * FH];
__device__ float g_y1[NN * FH];
__device__ float g_h2[NN * FOUT];
__device__ __half g_h1T[FH * NN];     // transposed fp16 h1
__device__ __half g_h2T[FOUT * NN];   // transposed fp16 h2
__device__ float g_s1[NN], g_t1[NN];
__device__ float g_s2[NN], g_t2[NN];
__device__ int g_tmaxi[2];
__device__ uint32_t g_adjbits[(size_t)NN * (NN / 32)];

__device__ __forceinline__ float elu1(float x) { return x > 0.f ? x : expm1f(x); }

// monotonic int encoding of float for deterministic atomicMax
__device__ __forceinline__ int enc_f(float f) {
    int i = __float_as_int(f);
    return i < 0 ? (i ^ 0x7fffffff) : i;
}
__device__ __forceinline__ float dec_f(int i) {
    return __int_as_float(i < 0 ? (i ^ 0x7fffffff) : i);
}

__device__ __forceinline__ void ldsm4(uint32_t& r0, uint32_t& r1, uint32_t& r2,
                                      uint32_t& r3, uint32_t addr) {
    asm volatile("ldmatrix.sync.aligned.m8n8.x4.shared.b16 {%0,%1,%2,%3}, [%4];"
                 : "=r"(r0), "=r"(r1), "=r"(r2), "=r"(r3) : "r"(addr));
}

__device__ __forceinline__ void mma16816(float d[4], uint32_t a0, uint32_t a1,
                                         uint32_t a2, uint32_t a3,
                                         uint32_t b0, uint32_t b1) {
    asm volatile(
        "mma.sync.aligned.m16n8k16.row.col.f32.f16.f16.f32 "
        "{%0,%1,%2,%3}, {%4,%5,%6,%7}, {%8,%9}, {%0,%1,%2,%3};"
        : "+f"(d[0]), "+f"(d[1]), "+f"(d[2]), "+f"(d[3])
        : "r"(a0), "r"(a1), "r"(a2), "r"(a3), "r"(b0), "r"(b1));
}

__device__ __forceinline__ void cp16(uint32_t dst, const void* src) {
    asm volatile("cp.async.cg.shared.global [%0], [%1], 16;" :: "r"(dst), "l"(src));
}

// =================================================================
// GEMM: C[M,N] = A[M,K] @ W[N,K]^T + bias[N]. Also re-inits tmax ints.
// =================================================================
__global__ __launch_bounds__(256) void gemm_bias(
    const float* __restrict__ A, const float* __restrict__ W,
    const float* __restrict__ bias, float* __restrict__ C,
    int M, int N, int K)
{
    const int BM = 128, BN = 64, BK = 16;
    __shared__ float As[BK][BM + 1];
    __shared__ float Bs[BK][BN + 1];

    int tid = threadIdx.x;
    int bx = blockIdx.x, by = blockIdx.y;
    if (bx == 0 && by == 0 && tid == 0) {
        g_tmaxi[0] = (int)0x80000000;
        g_tmaxi[1] = (int)0x80000000;
    }
    int ty = tid >> 4, tx = tid & 15;
    int ar = tid >> 2, ac4 = (tid & 3) * 4;

    float acc[8][4];
#pragma unroll
    for (int i = 0; i < 8; i++)
#pragma unroll
        for (int j = 0; j < 4; j++) acc[i][j] = 0.f;

    for (int k0 = 0; k0 < K; k0 += BK) {
        float4 a0 = *(const float4*)(A + (size_t)(by * BM + ar) * K + k0 + ac4);
        float4 a1 = *(const float4*)(A + (size_t)(by * BM + ar + 64) * K + k0 + ac4);
        float4 b0 = *(const float4*)(W + (size_t)(bx * BN + ar) * K + k0 + ac4);
        __syncthreads();
        As[ac4 + 0][ar] = a0.x; As[ac4 + 1][ar] = a0.y;
        As[ac4 + 2][ar] = a0.z; As[ac4 + 3][ar] = a0.w;
        As[ac4 + 0][ar + 64] = a1.x; As[ac4 + 1][ar + 64] = a1.y;
        As[ac4 + 2][ar + 64] = a1.z; As[ac4 + 3][ar + 64] = a1.w;
        Bs[ac4 + 0][ar] = b0.x; Bs[ac4 + 1][ar] = b0.y;
        Bs[ac4 + 2][ar] = b0.z; Bs[ac4 + 3][ar] = b0.w;
        __syncthreads();
#pragma unroll
        for (int k = 0; k < BK; k++) {
            float ra[8], rb[4];
#pragma unroll
            for (int i = 0; i < 8; i++) ra[i] = As[k][ty * 8 + i];
#pragma unroll
            for (int j = 0; j < 4; j++) rb[j] = Bs[k][tx * 4 + j];
#pragma unroll
            for (int i = 0; i < 8; i++)
#pragma unroll
                for (int j = 0; j < 4; j++) acc[i][j] = fmaf(ra[i], rb[j], acc[i][j]);
        }
    }

    float4 bv = ((const float4*)bias)[bx * 16 + tx];
#pragma unroll
    for (int i = 0; i < 8; i++) {
        int row = by * BM + ty * 8 + i;
        float4 v;
        v.x = acc[i][0] + bv.x; v.y = acc[i][1] + bv.y;
        v.z = acc[i][2] + bv.z; v.w = acc[i][3] + bv.w;
        ((float4*)(C + (size_t)row * N))[bx * 16 + tx] = v;
    }
}

// =================================================================
// transpose + fp16 convert (z==0); adjacency bit-pack (z==1)
// =================================================================
__global__ __launch_bounds__(256) void transpose_pack(
    const float* __restrict__ h, __half* __restrict__ hT, int F,
    const int* __restrict__ adj, uint32_t* __restrict__ bits)
{
    if (blockIdx.z == 1) {
        int bid = blockIdx.x + blockIdx.y * gridDim.x;   // 0..(gx*gy-1)
        int wd = threadIdx.x;                             // word 0..255
#pragma unroll
        for (int r = 0; r < 4; r++) {
            int row = bid * 4 + r;
            const int4* src = (const int4*)(adj + (size_t)row * NN + wd * 32);
            uint32_t m = 0;
#pragma unroll
            for (int q = 0; q < 8; q++) {
                int4 v = src[q];
                m |= (v.x != 0 ? 1u : 0u) << (q * 4 + 0);
                m |= (v.y != 0 ? 1u : 0u) << (q * 4 + 1);
                m |= (v.z != 0 ? 1u : 0u) << (q * 4 + 2);
                m |= (v.w != 0 ? 1u : 0u) << (q * 4 + 3);
            }
            bits[(size_t)row * (NN / 32) + wd] = m;
        }
        return;
    }

    __shared__ float ts[32][33];
    int n0 = blockIdx.x * 32, c0 = blockIdx.y * 32;
    int r = threadIdx.x >> 3, cc = (threadIdx.x & 7) * 4;

    float4 v = *(const float4*)(h + (size_t)(n0 + r) * F + c0 + cc);
    ts[r][cc + 0] = v.x; ts[r][cc + 1] = v.y;
    ts[r][cc + 2] = v.z; ts[r][cc + 3] = v.w;
    __syncthreads();

    int c = threadIdx.x >> 3, nn2 = (threadIdx.x & 7) * 4;
    __half2 p0 = __floats2half2_rn(ts[nn2 + 0][c], ts[nn2 + 1][c]);
    __half2 p1 = __floats2half2_rn(ts[nn2 + 2][c], ts[nn2 + 3][c]);
    union { __half2 h2[2]; uint2 u; } cv;
    cv.h2[0] = p0; cv.h2[1] = p1;
    *(uint2*)(hT + (size_t)(c0 + c) * NN + n0 + nn2) = cv.u;
}

// =================================================================
// s/t projections + deterministic integer atomicMax of t
// =================================================================
template <int F>
__global__ __launch_bounds__(256) void st_kernel(
    const float* __restrict__ h, const float* __restrict__ a,
    float* __restrict__ s, float* __restrict__ t, int* __restrict__ tmax)
{
    int warp = threadIdx.x >> 5, lane = threadIdx.x & 31;
    int row = blockIdx.x * 8 + warp;
    const float* hr = h + (size_t)row * F;
    float lo = 0.f, hi = 0.f;
#pragma unroll
    for (int f = lane; f < F; f += 32) {
        float v = hr[f];
        lo = fmaf(v, a[f], lo);
        hi = fmaf(v, a[F + f], hi);
    }
#pragma unroll
    for (int o = 16; o; o >>= 1) {
        lo += __shfl_xor_sync(0xffffffffu, lo, o);
        hi += __shfl_xor_sync(0xffffffffu, hi, o);
    }
    if (lane == 0) {
        s[row] = lo; t[row] = hi;
        atomicMax(tmax, enc_f(hi));
    }
}

// =================================================================
// Fused GAT attention, fp16 mma.sync + cp.async + ldmatrix.
// BJ=64 double-buffered, bit-packed adjacency mask.
// Dynamic smem: [Ht0][Ht1][Ps0][Ps1][lRow]
// 8 warps: warp (wr, wc) owns rows [16*wr, 16*wr+16) x col-half wc.
// =================================================================
template <int NF, bool FINAL>
__global__ __launch_bounds__(256) void attn_mma(
    const __half* __restrict__ hTg, const uint32_t* __restrict__ bits,
    const float* __restrict__ sG, const float* __restrict__ tG,
    const float* __restrict__ abG, const int* __restrict__ tmaxI,
    float* __restrict__ outG)
{
    constexpr int HTB = NF * 128;              // bytes per Ht buffer
    constexpr int PSB = 64 * 128;              // bytes per Ps buffer
    constexpr int LOFF = 2 * HTB + 2 * PSB;
    constexpr int NCT = NF / 16;               // 8-col mma tiles per warp
    constexpr int NQ = NCT / 2;                // ldmatrix.x4 B loads per k-step
    constexpr int PER = NF * 8 / 256;          // cp.async chunks per thread
    constexpr int NT = NN / 64;

    extern __shared__ char smem[];
    const uint32_t sb = (uint32_t)__cvta_generic_to_shared(smem);
    float* lRow = (float*)(smem + LOFF);

    const int tid = threadIdx.x;
    const int lane = tid & 31, w = tid >> 5;
    const int g = lane >> 2, tig = lane & 3;
    const int wr = w >> 1, wc = w & 1;
    const int R0 = wr * 16, C0 = wc * (NF / 2);
    const int i0 = blockIdx.x * 64;

    // phase-A mapping: thread (ar, acg) handles row ar, cols 16*acg..16*acg+15
    const int ar = tid >> 2, acg = tid & 3;
    const float sv = sG[i0 + ar] + abG[0];
    const float Ma = sv + dec_f(tmaxI[0]);
    const float M = fmaxf(Ma, LRELU_A * Ma);
    float lacc = 0.f;

    float acc[NCT][4];
#pragma unroll
    for (int c = 0; c < NCT; c++)
#pragma unroll
        for (int q = 0; q < 4; q++) acc[c][q] = 0.f;

    const uint32_t* brow = bits + (size_t)(i0 + ar) * (NN / 32);
    const int bsh = (acg & 1) * 16;            // which 16 bits of the word
    const uint32_t xr = (uint32_t)((ar & 7) << 4);          // phase-A write swizzle
    const uint32_t xO = (uint32_t)((lane & 7) << 4);        // ldmatrix row swizzle
    const int aRowB = R0 + (lane & 7) + ((lane >> 3) & 1) * 8;
    const uint32_t aBoff = (uint32_t)((lane >> 4) << 4);
    const int bColB = (lane & 7) + ((lane >> 4) << 3);
    const uint32_t bBoff = (uint32_t)(((lane >> 3) & 1) << 4);

    uint32_t bwv;
    float4 tv[4];

#define ISSUE_CP(J0, BUF) do {                                                 \
    uint32_t hb = sb + (BUF) * HTB;                                            \
    _Pragma("unroll")                                                          \
    for (int u = 0; u < PER; u++) {                                            \
        int ci = tid * PER + u;                                                \
        int rr = ci >> 3, ch = ci & 7;                                         \
        uint32_t dst = hb + rr * 128 +                                         \
                       (((uint32_t)(ch * 16)) ^ (((uint32_t)(rr & 7)) << 4));  \
        cp16(dst, hTg + (size_t)rr * NN + (J0) + ch * 8);                      \
    }                                                                          \
    asm volatile("cp.async.commit_group;" ::: "memory");                       \
} while (0)

#define LOAD_AT(J0) do {                                                       \
    bwv = brow[((J0) >> 5) + (acg >> 1)];                                      \
    _Pragma("unroll")                                                          \
    for (int q = 0; q < 4; q++)                                                \
        tv[q] = ((const float4*)(tG + (J0) + acg * 16))[q];                    \
} while (0)

#define PHASE_A(BUF) do {                                                      \
    float p[16];                                                               \
    uint32_t mb = bwv >> bsh;                                                  \
    const float* tf = (const float*)tv;                                        \
    _Pragma("unroll")                                                          \
    for (int k2 = 0; k2 < 16; k2++) {                                          \
        float e = sv + tf[k2];                                                 \
        e = fmaxf(e, LRELU_A * e);                                             \
        float pv = ((mb >> k2) & 1u) ? __expf(e - M) : 0.f;                    \
        p[k2] = pv; lacc += pv;                                                \
    }                                                                          \
    union { __half2 h2[8]; uint4 u[2]; } cvv;                                  \
    _Pragma("unroll")                                                          \
    for (int m2 = 0; m2 < 8; m2++)                                             \
        cvv.h2[m2] = __floats2half2_rn(p[2 * m2], p[2 * m2 + 1]);              \
    char* pbase = smem + 2 * HTB + (BUF) * PSB + ar * 128;                     \
    *(uint4*)(pbase + (((uint32_t)(acg * 32)) ^ xr)) = cvv.u[0];               \
    *(uint4*)(pbase + (((uint32_t)(acg * 32 + 16)) ^ xr)) = cvv.u[1];          \
} while (0)

    // ---- prologue: tile 0 ----
    ISSUE_CP(0, 0);
    LOAD_AT(0);
    PHASE_A(0);

    for (int i = 0; i < NT; i++) {
        __syncthreads();                       // Ps(i) written; mma(i-1) done
        asm volatile("cp.async.wait_group 0;" ::: "memory");
        __syncthreads();                       // Ht(i) visible to all warps

        const int cb = i & 1, nb = (i + 1) & 1;
        if (i + 1 < NT) {
            ISSUE_CP((i + 1) * 64, nb);
            LOAD_AT((i + 1) * 64);
        }

        // ---- mma(i): acc += P_tile @ H_tile ----
        const uint32_t psA = sb + 2 * HTB + cb * PSB + (uint32_t)aRowB * 128;
        const uint32_t htB = sb + cb * HTB;
#pragma unroll
        for (int k = 0; k < 4; k++) {
            uint32_t a0, a1, a2, a3;
            ldsm4(a0, a1, a2, a3, psA + ((((uint32_t)(32 * k)) + aBoff) ^ xO));
#pragma unroll
            for (int q = 0; q < NQ; q++) {
                uint32_t b0, b1, b2, b3;
                int c = C0 + 16 * q + bColB;
                ldsm4(b0, b1, b2, b3,
                      htB + (uint32_t)c * 128 + ((((uint32_t)(32 * k)) + bBoff) ^ xO));
                mma16816(acc[2 * q + 0], a0, a1, a2, a3, b0, b1);
                mma16816(acc[2 * q + 1], a0, a1, a2, a3, b2, b3);
            }
        }

        if (i + 1 < NT) PHASE_A(nb);
    }

    // ---- softmax denominators ----
    lacc += __shfl_xor_sync(0xffffffffu, lacc, 1);
    lacc += __shfl_xor_sync(0xffffffffu, lacc, 2);
    if (acg == 0) lRow[ar] = lacc;
    __syncthreads();

    const int r0 = R0 + g, r1 = R0 + 8 + g;
    const float inv0 = 1.f / lRow[r0];
    const float inv1 = 1.f / lRow[r1];

    if (!FINAL) {
#pragma unroll
        for (int ct = 0; ct < NCT; ct++) {
            int c = C0 + 8 * ct + 2 * tig;
            float2 v0 = make_float2(elu1(elu1(acc[ct][0] * inv0)),
                                    elu1(elu1(acc[ct][1] * inv0)));
            float2 v1 = make_float2(elu1(elu1(acc[ct][2] * inv1)),
                                    elu1(elu1(acc[ct][3] * inv1)));
            *(float2*)(outG + (size_t)(i0 + r0) * NF + c) = v0;
            *(float2*)(outG + (size_t)(i0 + r1) * NF + c) = v1;
        }
    } else {
        float* zs = (float*)smem;    // reuse Ht/Ps buffers (mma finished)
#pragma unroll
        for (int ct = 0; ct < NCT; ct++) {
            int c = C0 + 8 * ct + 2 * tig;
            *(float2*)&zs[r0 * 68 + c] = make_float2(elu1(acc[ct][0] * inv0),
                                                     elu1(acc[ct][1] * inv0));
            *(float2*)&zs[r1 * 68 + c] = make_float2(elu1(acc[ct][2] * inv1),
                                                     elu1(acc[ct][3] * inv1));
        }
        __syncthreads();
        int qr = tid >> 2, ql = tid & 3;
        float z[16];
#pragma unroll
        for (int i2 = 0; i2 < 4; i2++) {
            float4 v = *(float4*)&zs[qr * 68 + ql * 16 + 4 * i2];
            z[4 * i2] = v.x; z[4 * i2 + 1] = v.y;
            z[4 * i2 + 2] = v.z; z[4 * i2 + 3] = v.w;
        }
        float mx = z[0];
#pragma unroll
        for (int i2 = 1; i2 < 16; i2++) mx = fmaxf(mx, z[i2]);
        mx = fmaxf(mx, __shfl_xor_sync(0xffffffffu, mx, 1));
        mx = fmaxf(mx, __shfl_xor_sync(0xffffffffu, mx, 2));
        float se = 0.f;
#pragma unroll
        for (int i2 = 0; i2 < 16; i2++) se += __expf(z[i2] - mx);
        se += __shfl_xor_sync(0xffffffffu, se, 1);
        se += __shfl_xor_sync(0xffffffffu, se, 2);
        float lse = mx + logf(se);
#pragma unroll
        for (int i2 = 0; i2 < 4; i2++) {
            float4 o = make_float4(z[4 * i2] - lse, z[4 * i2 + 1] - lse,
                                   z[4 * i2 + 2] - lse, z[4 * i2 + 3] - lse);
            *(float4*)(outG + (size_t)(i0 + qr) * FOUT + ql * 16 + 4 * i2) = o;
        }
    }
#undef ISSUE_CP
#undef LOAD_AT
#undef PHASE_A
}

// =================================================================
extern "C" void kernel_launch(void* const* d_in, const int* in_sizes, int n_in,
                              void* d_out, int out_size)
{
    const float* x   = (const float*)d_in[0];
    const int*   adj = (const int*)  d_in[1];
    const float* W1  = (const float*)d_in[2];
    const float* b1  = (const float*)d_in[3];
    const float* a1  = (const float*)d_in[4];
    const float* ab1 = (const float*)d_in[5];
    const float* W2  = (const float*)d_in[6];
    const float* b2  = (const float*)d_in[7];
    const float* a2  = (const float*)d_in[8];
    const float* ab2 = (const float*)d_in[9];
    float* out = (float*)d_out;

    void *h1p, *y1p, *h2p, *h1tp, *h2tp, *s1p, *t1p, *s2p, *t2p, *tmp, *abp;
    cudaGetSymbolAddress(&h1p, g_h1);
    cudaGetSymbolAddress(&y1p, g_y1);
    cudaGetSymbolAddress(&h2p, g_h2);
    cudaGetSymbolAddress(&h1tp, g_h1T);
    cudaGetSymbolAddress(&h2tp, g_h2T);
    cudaGetSymbolAddress(&s1p, g_s1);
    cudaGetSymbolAddress(&t1p, g_t1);
    cudaGetSymbolAddress(&s2p, g_s2);
    cudaGetSymbolAddress(&t2p, g_t2);
    cudaGetSymbolAddress(&tmp, g_tmaxi);
    cudaGetSymbolAddress(&abp, g_adjbits);
    float* h1 = (float*)h1p; float* y1 = (float*)y1p; float* h2 = (float*)h2p;
    __half* h1T = (__half*)h1tp; __half* h2T = (__half*)h2tp;
    float* s1 = (float*)s1p; float* t1 = (float*)t1p;
    float* s2 = (float*)s2p; float* t2 = (float*)t2p;
    int* tmaxi = (int*)tmp;
    uint32_t* abits = (uint32_t*)abp;

    const int SM1 = 2 * (FH * 128) + 2 * 8192 + 256;    // 82176 bytes
    const int SM2 = 2 * (FOUT * 128) + 2 * 8192 + 256;  // 33024 bytes
    cudaFuncSetAttribute(attn_mma<FH, false>,
                         cudaFuncAttributeMaxDynamicSharedMemorySize, SM1);
    cudaFuncSetAttribute(attn_mma<FOUT, true>,
                         cudaFuncAttributeMaxDynamicSharedMemorySize, SM2);

    // Layer 1  (attn_mma<FH> is the 4th launch -> gets profiled by ncu)
    gemm_bias<<<dim3(FH / 64, NN / 128), 256>>>(x, W1, b1, h1, NN, FH, FIN);
    transpose_pack<<<dim3(NN / 32, FH / 32, 2), 256>>>(h1, h1T, FH, adj, abits);
    st_kernel<FH><<<NN / 8, 256>>>(h1, a1, s1, t1, tmaxi);
    attn_mma<FH, false><<<NN / 64, 256, SM1>>>(h1T, abits, s1, t1, ab1, tmaxi, y1);

    // Layer 2
    gemm_bias<<<dim3(FOUT / 64, NN / 128), 256>>>(y1, W2, b2, h2, NN, FOUT, FH);
    transpose_pack<<<dim3(NN / 32, FOUT / 32, 1), 256>>>(h2, h2T, FOUT, adj, abits);
    st_kernel<FOUT><<<NN / 8, 256>>>(h2, a2, s2, t2, tmaxi + 1);
    attn_mma<FOUT, true><<<NN / 64, 256, SM2>>>(h2T, abits, s2, t2, ab2, tmaxi + 1, out);
}

// round 9
// speedup vs baseline: 2.7123x; 1.1166x over previous
#include <cuda_runtime.h>
#include <cuda_fp16.h>
#include <math.h>
#include <stdint.h>

#define NN 8192
#define FIN 512
#define FH 256
#define FOUT 64
#define LRELU_A 0.2f

// ---------------- scratch (no allocations allowed) ----------------
__device__ float g_h1[NN * FH];
__device__ float g_y1[NN * FH];
__device__ float g_h2[NN * FOUT];
__device__ __half g_h1T[FH * NN];     // transposed fp16 h1
__device__ __half g_h2T[FOUT * NN];   // transposed fp16 h2
__device__ float g_s1[NN], g_t1[NN];
__device__ float g_s2[NN], g_t2[NN];
__device__ int g_tmaxi[2];
__device__ uint32_t g_adjbits[(size_t)NN * (NN / 32)];

__device__ __forceinline__ float elu1(float x) { return x > 0.f ? x : expm1f(x); }

// monotonic int encoding of float for deterministic atomicMax
__device__ __forceinline__ int enc_f(float f) {
    int i = __float_as_int(f);
    return i < 0 ? (i ^ 0x7fffffff) : i;
}
__device__ __forceinline__ float dec_f(int i) {
    return __int_as_float(i < 0 ? (i ^ 0x7fffffff) : i);
}

__device__ __forceinline__ void ldsm4(uint32_t& r0, uint32_t& r1, uint32_t& r2,
                                      uint32_t& r3, uint32_t addr) {
    asm volatile("ldmatrix.sync.aligned.m8n8.x4.shared.b16 {%0,%1,%2,%3}, [%4];"
                 : "=r"(r0), "=r"(r1), "=r"(r2), "=r"(r3) : "r"(addr));
}

__device__ __forceinline__ void mma16816(float d[4], uint32_t a0, uint32_t a1,
                                         uint32_t a2, uint32_t a3,
                                         uint32_t b0, uint32_t b1) {
    asm volatile(
        "mma.sync.aligned.m16n8k16.row.col.f32.f16.f16.f32 "
        "{%0,%1,%2,%3}, {%4,%5,%6,%7}, {%8,%9}, {%0,%1,%2,%3};"
        : "+f"(d[0]), "+f"(d[1]), "+f"(d[2]), "+f"(d[3])
        : "r"(a0), "r"(a1), "r"(a2), "r"(a3), "r"(b0), "r"(b1));
}

__device__ __forceinline__ void cp16(uint32_t dst, const void* src) {
    asm volatile("cp.async.cg.shared.global [%0], [%1], 16;" :: "r"(dst), "l"(src));
}

// =================================================================
// GEMM: C[M,N] = A[M,K] @ W[N,K]^T + bias[N]. Also re-inits tmax ints.
// =================================================================
__global__ __launch_bounds__(256) void gemm_bias(
    const float* __restrict__ A, const float* __restrict__ W,
    const float* __restrict__ bias, float* __restrict__ C,
    int M, int N, int K)
{
    const int BM = 128, BN = 64, BK = 16;
    __shared__ float As[BK][BM + 1];
    __shared__ float Bs[BK][BN + 1];

    int tid = threadIdx.x;
    int bx = blockIdx.x, by = blockIdx.y;
    if (bx == 0 && by == 0 && tid == 0) {
        g_tmaxi[0] = (int)0x80000000;
        g_tmaxi[1] = (int)0x80000000;
    }
    int ty = tid >> 4, tx = tid & 15;
    int ar = tid >> 2, ac4 = (tid & 3) * 4;

    float acc[8][4];
#pragma unroll
    for (int i = 0; i < 8; i++)
#pragma unroll
        for (int j = 0; j < 4; j++) acc[i][j] = 0.f;

    for (int k0 = 0; k0 < K; k0 += BK) {
        float4 a0 = *(const float4*)(A + (size_t)(by * BM + ar) * K + k0 + ac4);
        float4 a1 = *(const float4*)(A + (size_t)(by * BM + ar + 64) * K + k0 + ac4);
        float4 b0 = *(const float4*)(W + (size_t)(bx * BN + ar) * K + k0 + ac4);
        __syncthreads();
        As[ac4 + 0][ar] = a0.x; As[ac4 + 1][ar] = a0.y;
        As[ac4 + 2][ar] = a0.z; As[ac4 + 3][ar] = a0.w;
        As[ac4 + 0][ar + 64] = a1.x; As[ac4 + 1][ar + 64] = a1.y;
        As[ac4 + 2][ar + 64] = a1.z; As[ac4 + 3][ar + 64] = a1.w;
        Bs[ac4 + 0][ar] = b0.x; Bs[ac4 + 1][ar] = b0.y;
        Bs[ac4 + 2][ar] = b0.z; Bs[ac4 + 3][ar] = b0.w;
        __syncthreads();
#pragma unroll
        for (int k = 0; k < BK; k++) {
            float ra[8], rb[4];
#pragma unroll
            for (int i = 0; i < 8; i++) ra[i] = As[k][ty * 8 + i];
#pragma unroll
            for (int j = 0; j < 4; j++) rb[j] = Bs[k][tx * 4 + j];
#pragma unroll
            for (int i = 0; i < 8; i++)
#pragma unroll
                for (int j = 0; j < 4; j++) acc[i][j] = fmaf(ra[i], rb[j], acc[i][j]);
        }
    }

    float4 bv = ((const float4*)bias)[bx * 16 + tx];
#pragma unroll
    for (int i = 0; i < 8; i++) {
        int row = by * BM + ty * 8 + i;
        float4 v;
        v.x = acc[i][0] + bv.x; v.y = acc[i][1] + bv.y;
        v.z = acc[i][2] + bv.z; v.w = acc[i][3] + bv.w;
        ((float4*)(C + (size_t)row * N))[bx * 16 + tx] = v;
    }
}

// =================================================================
// transpose + fp16 convert (z==0); adjacency bit-pack (z==1)
// =================================================================
__global__ __launch_bounds__(256) void transpose_pack(
    const float* __restrict__ h, __half* __restrict__ hT, int F,
    const int* __restrict__ adj, uint32_t* __restrict__ bits)
{
    if (blockIdx.z == 1) {
        int bid = blockIdx.x + blockIdx.y * gridDim.x;
        int wd = threadIdx.x;
#pragma unroll
        for (int r = 0; r < 4; r++) {
            int row = bid * 4 + r;
            const int4* src = (const int4*)(adj + (size_t)row * NN + wd * 32);
            uint32_t m = 0;
#pragma unroll
            for (int q = 0; q < 8; q++) {
                int4 v = src[q];
                m |= (v.x != 0 ? 1u : 0u) << (q * 4 + 0);
                m |= (v.y != 0 ? 1u : 0u) << (q * 4 + 1);
                m |= (v.z != 0 ? 1u : 0u) << (q * 4 + 2);
                m |= (v.w != 0 ? 1u : 0u) << (q * 4 + 3);
            }
            bits[(size_t)row * (NN / 32) + wd] = m;
        }
        return;
    }

    __shared__ float ts[32][33];
    int n0 = blockIdx.x * 32, c0 = blockIdx.y * 32;
    int r = threadIdx.x >> 3, cc = (threadIdx.x & 7) * 4;

    float4 v = *(const float4*)(h + (size_t)(n0 + r) * F + c0 + cc);
    ts[r][cc + 0] = v.x; ts[r][cc + 1] = v.y;
    ts[r][cc + 2] = v.z; ts[r][cc + 3] = v.w;
    __syncthreads();

    int c = threadIdx.x >> 3, nn2 = (threadIdx.x & 7) * 4;
    __half2 p0 = __floats2half2_rn(ts[nn2 + 0][c], ts[nn2 + 1][c]);
    __half2 p1 = __floats2half2_rn(ts[nn2 + 2][c], ts[nn2 + 3][c]);
    union { __half2 h2[2]; uint2 u; } cv;
    cv.h2[0] = p0; cv.h2[1] = p1;
    *(uint2*)(hT + (size_t)(c0 + c) * NN + n0 + nn2) = cv.u;
}

// =================================================================
// s/t projections + deterministic integer atomicMax of t
// =================================================================
template <int F>
__global__ __launch_bounds__(256) void st_kernel(
    const float* __restrict__ h, const float* __restrict__ a,
    float* __restrict__ s, float* __restrict__ t, int* __restrict__ tmax)
{
    int warp = threadIdx.x >> 5, lane = threadIdx.x & 31;
    int row = blockIdx.x * 8 + warp;
    const float* hr = h + (size_t)row * F;
    float lo = 0.f, hi = 0.f;
#pragma unroll
    for (int f = lane; f < F; f += 32) {
        float v = hr[f];
        lo = fmaf(v, a[f], lo);
        hi = fmaf(v, a[F + f], hi);
    }
#pragma unroll
    for (int o = 16; o; o >>= 1) {
        lo += __shfl_xor_sync(0xffffffffu, lo, o);
        hi += __shfl_xor_sync(0xffffffffu, hi, o);
    }
    if (lane == 0) {
        s[row] = lo; t[row] = hi;
        atomicMax(tmax, enc_f(hi));
    }
}

// =================================================================
// Fused GAT attention, fp16 mma.sync + cp.async + ldmatrix.
// Generalized tiling: BM rows x NFB cols per CTA, NTH threads.
// BJ=64 double-buffered, bit-packed adjacency mask.
// Warp (wr, wc): rows [16*wr,16*wr+16) x cols [wc*PERCOL, ...).
// Phase A: TPR=8 threads per row, 8 j-cols per thread.
// =================================================================
template <int NF, int NFB, int BM, int NTH, bool FINAL>
__global__ __launch_bounds__(NTH, NTH == 256 ? 3 : 4) void attn_mma(
    const __half* __restrict__ hTg, const uint32_t* __restrict__ bits,
    const float* __restrict__ sG, const float* __restrict__ tG,
    const float* __restrict__ abG, const int* __restrict__ tmaxI,
    float* __restrict__ outG)
{
    constexpr int NW = NTH / 32;
    constexpr int WR = BM / 16;
    constexpr int WC = NW / WR;
    constexpr int PERCOL = NFB / WC;            // cols per warp
    constexpr int NCT = PERCOL / 8;             // 8-col mma tiles per warp
    constexpr int NQ = NCT / 2;                 // ldmatrix.x4 B loads per k-step
    constexpr int HTB = NFB * 128;              // bytes per Ht buffer
    constexpr int PSB = BM * 128;               // bytes per Ps buffer
    constexpr int LOFF = 2 * HTB + 2 * PSB;
    constexpr int PER = NFB * 8 / NTH;          // cp.async chunks per thread
    constexpr int NT = NN / 64;
    constexpr int NBLK = NF / NFB;

    extern __shared__ char smem[];
    const uint32_t sb = (uint32_t)__cvta_generic_to_shared(smem);
    float* lRow = (float*)(smem + LOFF);

    const int tid = threadIdx.x;
    const int lane = tid & 31, w = tid >> 5;
    const int g = lane >> 2, tig = lane & 3;
    const int wr = w / WC, wc = w % WC;
    const int R0 = wr * 16, C0 = wc * PERCOL;
    const int rb = blockIdx.x / NBLK, cb = blockIdx.x % NBLK;
    const int i0 = rb * BM, c0 = cb * NFB;

    // phase-A mapping: 8 threads per row, 8 cols per thread
    const int ar = tid >> 3, acg = tid & 7;
    const float sv = sG[i0 + ar] + abG[0];
    const float Ma = sv + dec_f(tmaxI[0]);
    const float M = fmaxf(Ma, LRELU_A * Ma);
    float lacc = 0.f;

    float acc[NCT][4];
#pragma unroll
    for (int c = 0; c < NCT; c++)
#pragma unroll
        for (int q = 0; q < 4; q++) acc[c][q] = 0.f;

    const uint32_t* brow = bits + (size_t)(i0 + ar) * (NN / 32);
    const int bsh = (acg & 3) * 8;              // which byte of the word
    const uint32_t xr = (uint32_t)((ar & 7) << 4);          // phase-A write swizzle
    const uint32_t xO = (uint32_t)((lane & 7) << 4);        // ldmatrix row swizzle
    const int aRowB = R0 + (lane & 7) + ((lane >> 3) & 1) * 8;
    const uint32_t aBoff = (uint32_t)((lane >> 4) << 4);
    const int bColB = (lane & 7) + ((lane >> 4) << 3);
    const uint32_t bBoff = (uint32_t)(((lane >> 3) & 1) << 4);

    uint32_t bwv;
    float4 tv[2];

#define ISSUE_CP(J0, BUF) do {                                                 \
    uint32_t hb = sb + (BUF) * HTB;                                            \
    _Pragma("unroll")                                                          \
    for (int u = 0; u < PER; u++) {                                            \
        int ci = tid * PER + u;                                                \
        int rr = ci >> 3, ch = ci & 7;                                         \
        uint32_t dst = hb + rr * 128 +                                         \
                       (((uint32_t)(ch * 16)) ^ (((uint32_t)(rr & 7)) << 4));  \
        cp16(dst, hTg + (size_t)(c0 + rr) * NN + (J0) + ch * 8);               \
    }                                                                          \
    asm volatile("cp.async.commit_group;" ::: "memory");                       \
} while (0)

#define LOAD_AT(J0) do {                                                       \
    bwv = brow[((J0) >> 5) + (acg >> 2)];                                      \
    tv[0] = ((const float4*)(tG + (J0) + acg * 8))[0];                         \
    tv[1] = ((const float4*)(tG + (J0) + acg * 8))[1];                         \
} while (0)

#define PHASE_A(BUF) do {                                                      \
    float p[8];                                                                \
    uint32_t mb = bwv >> bsh;                                                  \
    const float* tf = (const float*)tv;                                        \
    _Pragma("unroll")                                                          \
    for (int k2 = 0; k2 < 8; k2++) {                                           \
        float e = sv + tf[k2];                                                 \
        e = fmaxf(e, LRELU_A * e);                                             \
        float pv = ((mb >> k2) & 1u) ? __expf(e - M) : 0.f;                    \
        p[k2] = pv; lacc += pv;                                                \
    }                                                                          \
    union { __half2 h2[4]; uint4 u; } cvv;                                     \
    _Pragma("unroll")                                                          \
    for (int m2 = 0; m2 < 4; m2++)                                             \
        cvv.h2[m2] = __floats2half2_rn(p[2 * m2], p[2 * m2 + 1]);              \
    char* pbase = smem + 2 * HTB + (BUF) * PSB + ar * 128;                     \
    *(uint4*)(pbase + (((uint32_t)(acg * 16)) ^ xr)) = cvv.u;                  \
} while (0)

    // ---- prologue: tile 0 ----
    ISSUE_CP(0, 0);
    LOAD_AT(0);
    PHASE_A(0);

    for (int i = 0; i < NT; i++) {
        __syncthreads();                       // Ps(i) written; mma(i-1) done
        asm volatile("cp.async.wait_group 0;" ::: "memory");
        __syncthreads();                       // Ht(i) visible to all warps

        const int cbf = i & 1, nb = (i + 1) & 1;
        if (i + 1 < NT) {
            ISSUE_CP((i + 1) * 64, nb);
            LOAD_AT((i + 1) * 64);
        }

        // ---- mma(i): acc += P_tile @ H_tile ----
        const uint32_t psA = sb + 2 * HTB + cbf * PSB + (uint32_t)aRowB * 128;
        const uint32_t htB = sb + cbf * HTB;
#pragma unroll
        for (int k = 0; k < 4; k++) {
            uint32_t a0, a1, a2, a3;
            ldsm4(a0, a1, a2, a3, psA + ((((uint32_t)(32 * k)) + aBoff) ^ xO));
#pragma unroll
            for (int q = 0; q < NQ; q++) {
                uint32_t b0, b1, b2, b3;
                int c = C0 + 16 * q + bColB;
                ldsm4(b0, b1, b2, b3,
                      htB + (uint32_t)c * 128 + ((((uint32_t)(32 * k)) + bBoff) ^ xO));
                mma16816(acc[2 * q + 0], a0, a1, a2, a3, b0, b1);
                mma16816(acc[2 * q + 1], a0, a1, a2, a3, b2, b3);
            }
        }

        if (i + 1 < NT) PHASE_A(nb);
    }

    // ---- softmax denominators (reduce over 8 threads per row) ----
    lacc += __shfl_xor_sync(0xffffffffu, lacc, 1);
    lacc += __shfl_xor_sync(0xffffffffu, lacc, 2);
    lacc += __shfl_xor_sync(0xffffffffu, lacc, 4);
    if (acg == 0) lRow[ar] = lacc;
    __syncthreads();

    const int r0 = R0 + g, r1 = R0 + 8 + g;
    const float inv0 = 1.f / lRow[r0];
    const float inv1 = 1.f / lRow[r1];

    if (!FINAL) {
#pragma unroll
        for (int ct = 0; ct < NCT; ct++) {
            int c = c0 + C0 + 8 * ct + 2 * tig;
            float2 v0 = make_float2(elu1(elu1(acc[ct][0] * inv0)),
                                    elu1(elu1(acc[ct][1] * inv0)));
            float2 v1 = make_float2(elu1(elu1(acc[ct][2] * inv1)),
                                    elu1(elu1(acc[ct][3] * inv1)));
            *(float2*)(outG + (size_t)(i0 + r0) * NF + c) = v0;
            *(float2*)(outG + (size_t)(i0 + r1) * NF + c) = v1;
        }
    } else {
        float* zs = (float*)smem;    // reuse Ht0 buffer (mma reads Ht1/Ps1 last)
#pragma unroll
        for (int ct = 0; ct < NCT; ct++) {
            int c = C0 + 8 * ct + 2 * tig;
            *(float2*)&zs[r0 * 68 + c] = make_float2(elu1(acc[ct][0] * inv0),
                                                     elu1(acc[ct][1] * inv0));
            *(float2*)&zs[r1 * 68 + c] = make_float2(elu1(acc[ct][2] * inv1),
                                                     elu1(acc[ct][3] * inv1));
        }
        __syncthreads();
        // per-row log_softmax over NF=64 cols; 8 threads per row, 8 cols each
        int qr = tid >> 3, ql = tid & 7;
        float z[8];
        {
            float4 v0 = *(float4*)&zs[qr * 68 + ql * 8 + 0];
            float4 v1 = *(float4*)&zs[qr * 68 + ql * 8 + 4];
            z[0] = v0.x; z[1] = v0.y; z[2] = v0.z; z[3] = v0.w;
            z[4] = v1.x; z[5] = v1.y; z[6] = v1.z; z[7] = v1.w;
        }
        float mx = z[0];
#pragma unroll
        for (int i2 = 1; i2 < 8; i2++) mx = fmaxf(mx, z[i2]);
        mx = fmaxf(mx, __shfl_xor_sync(0xffffffffu, mx, 1));
        mx = fmaxf(mx, __shfl_xor_sync(0xffffffffu, mx, 2));
        mx = fmaxf(mx, __shfl_xor_sync(0xffffffffu, mx, 4));
        float se = 0.f;
#pragma unroll
        for (int i2 = 0; i2 < 8; i2++) se += __expf(z[i2] - mx);
        se += __shfl_xor_sync(0xffffffffu, se, 1);
        se += __shfl_xor_sync(0xffffffffu, se, 2);
        se += __shfl_xor_sync(0xffffffffu, se, 4);
        float lse = mx + logf(se);
        float4 o0 = make_float4(z[0] - lse, z[1] - lse, z[2] - lse, z[3] - lse);
        float4 o1 = make_float4(z[4] - lse, z[5] - lse, z[6] - lse, z[7] - lse);
        float* op = outG + (size_t)(i0 + qr) * FOUT + ql * 8;
        ((float4*)op)[0] = o0;
        ((float4*)op)[1] = o1;
    }
#undef ISSUE_CP
#undef LOAD_AT
#undef PHASE_A
}

// =================================================================
extern "C" void kernel_launch(void* const* d_in, const int* in_sizes, int n_in,
                              void* d_out, int out_size)
{
    const float* x   = (const float*)d_in[0];
    const int*   adj = (const int*)  d_in[1];
    const float* W1  = (const float*)d_in[2];
    const float* b1  = (const float*)d_in[3];
    const float* a1  = (const float*)d_in[4];
    const float* ab1 = (const float*)d_in[5];
    const float* W2  = (const float*)d_in[6];
    const float* b2  = (const float*)d_in[7];
    const float* a2  = (const float*)d_in[8];
    const float* ab2 = (const float*)d_in[9];
    float* out = (float*)d_out;

    void *h1p, *y1p, *h2p, *h1tp, *h2tp, *s1p, *t1p, *s2p, *t2p, *tmp, *abp;
    cudaGetSymbolAddress(&h1p, g_h1);
    cudaGetSymbolAddress(&y1p, g_y1);
    cudaGetSymbolAddress(&h2p, g_h2);
    cudaGetSymbolAddress(&h1tp, g_h1T);
    cudaGetSymbolAddress(&h2tp, g_h2T);
    cudaGetSymbolAddress(&s1p, g_s1);
    cudaGetSymbolAddress(&t1p, g_t1);
    cudaGetSymbolAddress(&s2p, g_s2);
    cudaGetSymbolAddress(&t2p, g_t2);
    cudaGetSymbolAddress(&tmp, g_tmaxi);
    cudaGetSymbolAddress(&abp, g_adjbits);
    float* h1 = (float*)h1p; float* y1 = (float*)y1p; float* h2 = (float*)h2p;
    __half* h1T = (__half*)h1tp; __half* h2T = (__half*)h2tp;
    float* s1 = (float*)s1p; float* t1 = (float*)t1p;
    float* s2 = (float*)s2p; float* t2 = (float*)t2p;
    int* tmaxi = (int*)tmp;
    uint32_t* abits = (uint32_t*)abp;

    // attn1: BM=32, NFB=128, 256 threads; attn2: BM=16, NFB=64, 128 threads
    const int SM1 = 2 * (128 * 128) + 2 * (32 * 128) + 256;   // 41216 bytes
    const int SM2 = 2 * (64 * 128) + 2 * (16 * 128) + 256;    // 20736 bytes
    cudaFuncSetAttribute((const void*)attn_mma<FH, 128, 32, 256, false>,
                         cudaFuncAttributeMaxDynamicSharedMemorySize, SM1);
    cudaFuncSetAttribute((const void*)attn_mma<FOUT, 64, 16, 128, true>,
                         cudaFuncAttributeMaxDynamicSharedMemorySize, SM2);

    // Layer 1  (attn_mma is the 4th launch -> gets profiled by ncu)
    gemm_bias<<<dim3(FH / 64, NN / 128), 256>>>(x, W1, b1, h1, NN, FH, FIN);
    transpose_pack<<<dim3(NN / 32, FH / 32, 2), 256>>>(h1, h1T, FH, adj, abits);
    st_kernel<FH><<<NN / 8, 256>>>(h1, a1, s1, t1, tmaxi);
    attn_mma<FH, 128, 32, 256, false><<<(NN / 32) * 2, 256, SM1>>>(
        h1T, abits, s1, t1, ab1, tmaxi, y1);

    // Layer 2
    gemm_bias<<<dim3(FOUT / 64, NN / 128), 256>>>(y1, W2, b2, h2, NN, FOUT, FH);
    transpose_pack<<<dim3(NN / 32, FOUT / 32, 1), 256>>>(h2, h2T, FOUT, adj, abits);
    st_kernel<FOUT><<<NN / 8, 256>>>(h2, a2, s2, t2, tmaxi + 1);
    attn_mma<FOUT, 64, 16, 128, true><<<NN / 16, 128, SM2>>>(
        h2T, abits, s2, t2, ab2, tmaxi + 1, out);
}

// round 10
// speedup vs baseline: 3.0221x; 1.1142x over previous
#include <cuda_runtime.h>
#include <cuda_fp16.h>
#include <math.h>
#include <stdint.h>

#define NN 8192
#define FIN 512
#define FH 256
#define FOUT 64
#define LRELU_A 0.2f

// ---------------- scratch (no allocations allowed) ----------------
__device__ float g_h1[NN * FH];
__device__ float g_y1[NN * FH];
__device__ float g_h2[NN * FOUT];
__device__ __half g_h1T[FH * NN];     // transposed fp16 h1
__device__ __half g_h2T[FOUT * NN];   // transposed fp16 h2
__device__ float g_s1[NN], g_t1[NN];
__device__ float g_s2[NN], g_t2[NN];
__device__ int g_tmaxi[2];
__device__ uint32_t g_adjbits[(size_t)NN * (NN / 32)];

__device__ __forceinline__ float elu1(float x) { return x > 0.f ? x : expm1f(x); }

// monotonic int encoding of float for deterministic atomicMax
__device__ __forceinline__ int enc_f(float f) {
    int i = __float_as_int(f);
    return i < 0 ? (i ^ 0x7fffffff) : i;
}
__device__ __forceinline__ float dec_f(int i) {
    return __int_as_float(i < 0 ? (i ^ 0x7fffffff) : i);
}

__device__ __forceinline__ void ldsm4(uint32_t& r0, uint32_t& r1, uint32_t& r2,
                                      uint32_t& r3, uint32_t addr) {
    asm volatile("ldmatrix.sync.aligned.m8n8.x4.shared.b16 {%0,%1,%2,%3}, [%4];"
                 : "=r"(r0), "=r"(r1), "=r"(r2), "=r"(r3) : "r"(addr));
}

__device__ __forceinline__ void mma16816(float d[4], uint32_t a0, uint32_t a1,
                                         uint32_t a2, uint32_t a3,
                                         uint32_t b0, uint32_t b1) {
    asm volatile(
        "mma.sync.aligned.m16n8k16.row.col.f32.f16.f16.f32 "
        "{%0,%1,%2,%3}, {%4,%5,%6,%7}, {%8,%9}, {%0,%1,%2,%3};"
        : "+f"(d[0]), "+f"(d[1]), "+f"(d[2]), "+f"(d[3])
        : "r"(a0), "r"(a1), "r"(a2), "r"(a3), "r"(b0), "r"(b1));
}

__device__ __forceinline__ void cp16(uint32_t dst, const void* src) {
    asm volatile("cp.async.cg.shared.global [%0], [%1], 16;" :: "r"(dst), "l"(src));
}

// =================================================================
// GEMM: C[M,N] = A[M,K] @ W[N,K]^T + bias[N]. Also re-inits tmax ints.
// =================================================================
__global__ __launch_bounds__(256) void gemm_bias(
    const float* __restrict__ A, const float* __restrict__ W,
    const float* __restrict__ bias, float* __restrict__ C,
    int M, int N, int K)
{
    const int BM = 128, BN = 64, BK = 16;
    __shared__ float As[BK][BM + 1];
    __shared__ float Bs[BK][BN + 1];

    int tid = threadIdx.x;
    int bx = blockIdx.x, by = blockIdx.y;
    if (bx == 0 && by == 0 && tid == 0) {
        g_tmaxi[0] = (int)0x80000000;
        g_tmaxi[1] = (int)0x80000000;
    }
    int ty = tid >> 4, tx = tid & 15;
    int ar = tid >> 2, ac4 = (tid & 3) * 4;

    float acc[8][4];
#pragma unroll
    for (int i = 0; i < 8; i++)
#pragma unroll
        for (int j = 0; j < 4; j++) acc[i][j] = 0.f;

    for (int k0 = 0; k0 < K; k0 += BK) {
        float4 a0 = *(const float4*)(A + (size_t)(by * BM + ar) * K + k0 + ac4);
        float4 a1 = *(const float4*)(A + (size_t)(by * BM + ar + 64) * K + k0 + ac4);
        float4 b0 = *(const float4*)(W + (size_t)(bx * BN + ar) * K + k0 + ac4);
        __syncthreads();
        As[ac4 + 0][ar] = a0.x; As[ac4 + 1][ar] = a0.y;
        As[ac4 + 2][ar] = a0.z; As[ac4 + 3][ar] = a0.w;
        As[ac4 + 0][ar + 64] = a1.x; As[ac4 + 1][ar + 64] = a1.y;
        As[ac4 + 2][ar + 64] = a1.z; As[ac4 + 3][ar + 64] = a1.w;
        Bs[ac4 + 0][ar] = b0.x; Bs[ac4 + 1][ar] = b0.y;
        Bs[ac4 + 2][ar] = b0.z; Bs[ac4 + 3][ar] = b0.w;
        __syncthreads();
#pragma unroll
        for (int k = 0; k < BK; k++) {
            float ra[8], rb[4];
#pragma unroll
            for (int i = 0; i < 8; i++) ra[i] = As[k][ty * 8 + i];
#pragma unroll
            for (int j = 0; j < 4; j++) rb[j] = Bs[k][tx * 4 + j];
#pragma unroll
            for (int i = 0; i < 8; i++)
#pragma unroll
                for (int j = 0; j < 4; j++) acc[i][j] = fmaf(ra[i], rb[j], acc[i][j]);
        }
    }

    float4 bv = ((const float4*)bias)[bx * 16 + tx];
#pragma unroll
    for (int i = 0; i < 8; i++) {
        int row = by * BM + ty * 8 + i;
        float4 v;
        v.x = acc[i][0] + bv.x; v.y = acc[i][1] + bv.y;
        v.z = acc[i][2] + bv.z; v.w = acc[i][3] + bv.w;
        ((float4*)(C + (size_t)row * N))[bx * 16 + tx] = v;
    }
}

// =================================================================
// transpose + fp16 convert (z==0); adjacency bit-pack (z==1)
// =================================================================
__global__ __launch_bounds__(256) void transpose_pack(
    const float* __restrict__ h, __half* __restrict__ hT, int F,
    const int* __restrict__ adj, uint32_t* __restrict__ bits)
{
    if (blockIdx.z == 1) {
        int bid = blockIdx.x + blockIdx.y * gridDim.x;
        int wd = threadIdx.x;
#pragma unroll
        for (int r = 0; r < 4; r++) {
            int row = bid * 4 + r;
            const int4* src = (const int4*)(adj + (size_t)row * NN + wd * 32);
            uint32_t m = 0;
#pragma unroll
            for (int q = 0; q < 8; q++) {
                int4 v = src[q];
                m |= (v.x != 0 ? 1u : 0u) << (q * 4 + 0);
                m |= (v.y != 0 ? 1u : 0u) << (q * 4 + 1);
                m |= (v.z != 0 ? 1u : 0u) << (q * 4 + 2);
                m |= (v.w != 0 ? 1u : 0u) << (q * 4 + 3);
            }
            bits[(size_t)row * (NN / 32) + wd] = m;
        }
        return;
    }

    __shared__ float ts[32][33];
    int n0 = blockIdx.x * 32, c0 = blockIdx.y * 32;
    int r = threadIdx.x >> 3, cc = (threadIdx.x & 7) * 4;

    float4 v = *(const float4*)(h + (size_t)(n0 + r) * F + c0 + cc);
    ts[r][cc + 0] = v.x; ts[r][cc + 1] = v.y;
    ts[r][cc + 2] = v.z; ts[r][cc + 3] = v.w;
    __syncthreads();

    int c = threadIdx.x >> 3, nn2 = (threadIdx.x & 7) * 4;
    __half2 p0 = __floats2half2_rn(ts[nn2 + 0][c], ts[nn2 + 1][c]);
    __half2 p1 = __floats2half2_rn(ts[nn2 + 2][c], ts[nn2 + 3][c]);
    union { __half2 h2[2]; uint2 u; } cv;
    cv.h2[0] = p0; cv.h2[1] = p1;
    *(uint2*)(hT + (size_t)(c0 + c) * NN + n0 + nn2) = cv.u;
}

// =================================================================
// s/t projections + deterministic integer atomicMax of t
// =================================================================
template <int F>
__global__ __launch_bounds__(256) void st_kernel(
    const float* __restrict__ h, const float* __restrict__ a,
    float* __restrict__ s, float* __restrict__ t, int* __restrict__ tmax)
{
    int warp = threadIdx.x >> 5, lane = threadIdx.x & 31;
    int row = blockIdx.x * 8 + warp;
    const float* hr = h + (size_t)row * F;
    float lo = 0.f, hi = 0.f;
#pragma unroll
    for (int f = lane; f < F; f += 32) {
        float v = hr[f];
        lo = fmaf(v, a[f], lo);
        hi = fmaf(v, a[F + f], hi);
    }
#pragma unroll
    for (int o = 16; o; o >>= 1) {
        lo += __shfl_xor_sync(0xffffffffu, lo, o);
        hi += __shfl_xor_sync(0xffffffffu, hi, o);
    }
    if (lane == 0) {
        s[row] = lo; t[row] = hi;
        atomicMax(tmax, enc_f(hi));
    }
}

// =================================================================
// Fused GAT attention, fp16 mma.sync + cp.async + ldmatrix.
// BM rows x NFB cols per CTA, NTH threads, TPI 64-j subtiles per
// iteration, double-buffered, single barrier per iteration.
// =================================================================
template <int NF, int NFB, int BM, int NTH, int TPI, int MINB, bool FINAL>
__global__ __launch_bounds__(NTH, MINB) void attn_mma(
    const __half* __restrict__ hTg, const uint32_t* __restrict__ bits,
    const float* __restrict__ sG, const float* __restrict__ tG,
    const float* __restrict__ abG, const int* __restrict__ tmaxI,
    float* __restrict__ outG)
{
    constexpr int NW = NTH / 32;
    constexpr int WR = BM / 16;
    constexpr int WC = NW / WR;
    constexpr int PERCOL = NFB / WC;            // cols per warp
    constexpr int NCT = PERCOL / 8;             // 8-col mma tiles per warp
    constexpr int NQ = NCT / 2;                 // ldmatrix.x4 B loads per k-step
    constexpr int THT = NFB * 128;              // bytes per Ht subtile
    constexpr int TPS = BM * 128;               // bytes per Ps subtile
    constexpr int HTB = TPI * THT;              // bytes per Ht buffer
    constexpr int PSB = TPI * TPS;              // bytes per Ps buffer
    constexpr int LOFF = 2 * HTB + 2 * PSB;
    constexpr int PERT = NFB * 8 / NTH;         // cp chunks per thread per subtile
    constexpr int NIT = NN / (64 * TPI);
    constexpr int NBLK = NF / NFB;

    extern __shared__ char smem[];
    const uint32_t sb = (uint32_t)__cvta_generic_to_shared(smem);
    float* lRow = (float*)(smem + LOFF);

    const int tid = threadIdx.x;
    const int lane = tid & 31, w = tid >> 5;
    const int g = lane >> 2, tig = lane & 3;
    const int wr = w / WC, wc = w % WC;
    const int R0 = wr * 16, C0 = wc * PERCOL;
    const int rb = blockIdx.x / NBLK, cb = blockIdx.x % NBLK;
    const int i0 = rb * BM, c0 = cb * NFB;

    // phase-A mapping: 8 threads per row, 8 j-cols per thread per subtile
    const int ar = tid >> 3, acg = tid & 7;
    const float sv = sG[i0 + ar] + abG[0];
    const float Ma = sv + dec_f(tmaxI[0]);
    const float M = fmaxf(Ma, LRELU_A * Ma);
    float lacc = 0.f;

    float acc[NCT][4];
#pragma unroll
    for (int c = 0; c < NCT; c++)
#pragma unroll
        for (int q = 0; q < 4; q++) acc[c][q] = 0.f;

    const uint32_t* brow = bits + (size_t)(i0 + ar) * (NN / 32);
    const int bsh = (acg & 3) * 8;
    const uint32_t xr = (uint32_t)((ar & 7) << 4);          // phase-A write swizzle
    const uint32_t xO = (uint32_t)((lane & 7) << 4);        // ldmatrix row swizzle
    const int aRowB = R0 + (lane & 7) + ((lane >> 3) & 1) * 8;
    const uint32_t aBoff = (uint32_t)((lane >> 4) << 4);
    const int bColB = (lane & 7) + ((lane >> 4) << 3);
    const uint32_t bBoff = (uint32_t)(((lane >> 3) & 1) << 4);

    uint32_t bwv[TPI];
    float4 tvv[TPI][2];

#define ISSUE_CP(J0, BUF) do {                                                 \
    uint32_t hb = sb + (BUF) * HTB;                                            \
    _Pragma("unroll")                                                          \
    for (int tp = 0; tp < TPI; tp++) {                                         \
        _Pragma("unroll")                                                      \
        for (int u = 0; u < PERT; u++) {                                       \
            int ci = tid * PERT + u;                                           \
            int rr = ci >> 3, ch = ci & 7;                                     \
            uint32_t dst = hb + tp * THT + rr * 128 +                          \
                           (((uint32_t)(ch * 16)) ^ (((uint32_t)(rr & 7)) << 4)); \
            cp16(dst, hTg + (size_t)(c0 + rr) * NN + (J0) + tp * 64 + ch * 8); \
        }                                                                      \
    }                                                                          \
    asm volatile("cp.async.commit_group;" ::: "memory");                       \
} while (0)

#define LOAD_AT(J0) do {                                                       \
    _Pragma("unroll")                                                          \
    for (int tp = 0; tp < TPI; tp++) {                                         \
        bwv[tp] = brow[(((J0) + tp * 64) >> 5) + (acg >> 2)];                  \
        tvv[tp][0] = ((const float4*)(tG + (J0) + tp * 64 + acg * 8))[0];      \
        tvv[tp][1] = ((const float4*)(tG + (J0) + tp * 64 + acg * 8))[1];      \
    }                                                                          \
} while (0)

#define PHASE_A(BUF) do {                                                      \
    _Pragma("unroll")                                                          \
    for (int tp = 0; tp < TPI; tp++) {                                         \
        float p[8];                                                            \
        uint32_t mb = bwv[tp] >> bsh;                                          \
        const float* tf = (const float*)&tvv[tp][0];                           \
        _Pragma("unroll")                                                      \
        for (int k2 = 0; k2 < 8; k2++) {                                       \
            float e = sv + tf[k2];                                             \
            e = fmaxf(e, LRELU_A * e);                                         \
            float pv = ((mb >> k2) & 1u) ? __expf(e - M) : 0.f;                \
            p[k2] = pv; lacc += pv;                                            \
        }                                                                      \
        union { __half2 h2[4]; uint4 u; } cvv;                                 \
        _Pragma("unroll")                                                      \
        for (int m2 = 0; m2 < 4; m2++)                                         \
            cvv.h2[m2] = __floats2half2_rn(p[2 * m2], p[2 * m2 + 1]);          \
        char* pbase = smem + 2 * HTB + (BUF) * PSB + tp * TPS + ar * 128;      \
        *(uint4*)(pbase + (((uint32_t)(acg * 16)) ^ xr)) = cvv.u;              \
    }                                                                          \
} while (0)

    // ---- prologue: iteration 0 ----
    ISSUE_CP(0, 0);
    LOAD_AT(0);
    PHASE_A(0);

    for (int i = 0; i < NIT; i++) {
        // single barrier: per-warp cp drain + block-wide publish
        asm volatile("cp.async.wait_group 0;" ::: "memory");
        __syncthreads();

        const int cbf = i & 1, nb = (i + 1) & 1;
        if (i + 1 < NIT) {
            ISSUE_CP((i + 1) * 64 * TPI, nb);
            LOAD_AT((i + 1) * 64 * TPI);
        }

        // ---- mma(i): acc += P_subtiles @ H_subtiles ----
#pragma unroll
        for (int tp = 0; tp < TPI; tp++) {
            const uint32_t psA = sb + 2 * HTB + cbf * PSB + tp * TPS +
                                 (uint32_t)aRowB * 128;
            const uint32_t htB = sb + cbf * HTB + tp * THT;
#pragma unroll
            for (int k = 0; k < 4; k++) {
                uint32_t a0, a1, a2, a3;
                ldsm4(a0, a1, a2, a3, psA + ((((uint32_t)(32 * k)) + aBoff) ^ xO));
#pragma unroll
                for (int q = 0; q < NQ; q++) {
                    uint32_t b0, b1, b2, b3;
                    int c = C0 + 16 * q + bColB;
                    ldsm4(b0, b1, b2, b3,
                          htB + (uint32_t)c * 128 + ((((uint32_t)(32 * k)) + bBoff) ^ xO));
                    mma16816(acc[2 * q + 0], a0, a1, a2, a3, b0, b1);
                    mma16816(acc[2 * q + 1], a0, a1, a2, a3, b2, b3);
                }
            }
        }

        if (i + 1 < NIT) PHASE_A(nb);
    }

    // ---- softmax denominators (reduce over 8 threads per row) ----
    lacc += __shfl_xor_sync(0xffffffffu, lacc, 1);
    lacc += __shfl_xor_sync(0xffffffffu, lacc, 2);
    lacc += __shfl_xor_sync(0xffffffffu, lacc, 4);
    if (acg == 0) lRow[ar] = lacc;
    __syncthreads();

    const int r0 = R0 + g, r1 = R0 + 8 + g;
    const float inv0 = 1.f / lRow[r0];
    const float inv1 = 1.f / lRow[r1];

    if (!FINAL) {
#pragma unroll
        for (int ct = 0; ct < NCT; ct++) {
            int c = c0 + C0 + 8 * ct + 2 * tig;
            float2 v0 = make_float2(elu1(elu1(acc[ct][0] * inv0)),
                                    elu1(elu1(acc[ct][1] * inv0)));
            float2 v1 = make_float2(elu1(elu1(acc[ct][2] * inv1)),
                                    elu1(elu1(acc[ct][3] * inv1)));
            *(float2*)(outG + (size_t)(i0 + r0) * NF + c) = v0;
            *(float2*)(outG + (size_t)(i0 + r1) * NF + c) = v1;
        }
    } else {
        float* zs = (float*)smem;    // reuse buffers (all mma done)
#pragma unroll
        for (int ct = 0; ct < NCT; ct++) {
            int c = C0 + 8 * ct + 2 * tig;
            *(float2*)&zs[r0 * 68 + c] = make_float2(elu1(acc[ct][0] * inv0),
                                                     elu1(acc[ct][1] * inv0));
            *(float2*)&zs[r1 * 68 + c] = make_float2(elu1(acc[ct][2] * inv1),
                                                     elu1(acc[ct][3] * inv1));
        }
        __syncthreads();
        // per-row log_softmax over NF=64 cols; 8 threads per row, 8 cols each
        int qr = tid >> 3, ql = tid & 7;
        float z[8];
        {
            float4 v0 = *(float4*)&zs[qr * 68 + ql * 8 + 0];
            float4 v1 = *(float4*)&zs[qr * 68 + ql * 8 + 4];
            z[0] = v0.x; z[1] = v0.y; z[2] = v0.z; z[3] = v0.w;
            z[4] = v1.x; z[5] = v1.y; z[6] = v1.z; z[7] = v1.w;
        }
        float mx = z[0];
#pragma unroll
        for (int i2 = 1; i2 < 8; i2++) mx = fmaxf(mx, z[i2]);
        mx = fmaxf(mx, __shfl_xor_sync(0xffffffffu, mx, 1));
        mx = fmaxf(mx, __shfl_xor_sync(0xffffffffu, mx, 2));
        mx = fmaxf(mx, __shfl_xor_sync(0xffffffffu, mx, 4));
        float se = 0.f;
#pragma unroll
        for (int i2 = 0; i2 < 8; i2++) se += __expf(z[i2] - mx);
        se += __shfl_xor_sync(0xffffffffu, se, 1);
        se += __shfl_xor_sync(0xffffffffu, se, 2);
        se += __shfl_xor_sync(0xffffffffu, se, 4);
        float lse = mx + logf(se);
        float4 o0 = make_float4(z[0] - lse, z[1] - lse, z[2] - lse, z[3] - lse);
        float4 o1 = make_float4(z[4] - lse, z[5] - lse, z[6] - lse, z[7] - lse);
        float* op = outG + (size_t)(i0 + qr) * FOUT + ql * 8;
        ((float4*)op)[0] = o0;
        ((float4*)op)[1] = o1;
    }
#undef ISSUE_CP
#undef LOAD_AT
#undef PHASE_A
}

// =================================================================
extern "C" void kernel_launch(void* const* d_in, const int* in_sizes, int n_in,
                              void* d_out, int out_size)
{
    const float* x   = (const float*)d_in[0];
    const int*   adj = (const int*)  d_in[1];
    const float* W1  = (const float*)d_in[2];
    const float* b1  = (const float*)d_in[3];
    const float* a1  = (const float*)d_in[4];
    const float* ab1 = (const float*)d_in[5];
    const float* W2  = (const float*)d_in[6];
    const float* b2  = (const float*)d_in[7];
    const float* a2  = (const float*)d_in[8];
    const float* ab2 = (const float*)d_in[9];
    float* out = (float*)d_out;

    void *h1p, *y1p, *h2p, *h1tp, *h2tp, *s1p, *t1p, *s2p, *t2p, *tmp, *abp;
    cudaGetSymbolAddress(&h1p, g_h1);
    cudaGetSymbolAddress(&y1p, g_y1);
    cudaGetSymbolAddress(&h2p, g_h2);
    cudaGetSymbolAddress(&h1tp, g_h1T);
    cudaGetSymbolAddress(&h2tp, g_h2T);
    cudaGetSymbolAddress(&s1p, g_s1);
    cudaGetSymbolAddress(&t1p, g_t1);
    cudaGetSymbolAddress(&s2p, g_s2);
    cudaGetSymbolAddress(&t2p, g_t2);
    cudaGetSymbolAddress(&tmp, g_tmaxi);
    cudaGetSymbolAddress(&abp, g_adjbits);
    float* h1 = (float*)h1p; float* y1 = (float*)y1p; float* h2 = (float*)h2p;
    __half* h1T = (__half*)h1tp; __half* h2T = (__half*)h2tp;
    float* s1 = (float*)s1p; float* t1 = (float*)t1p;
    float* s2 = (float*)s2p; float* t2 = (float*)t2p;
    int* tmaxi = (int*)tmp;
    uint32_t* abits = (uint32_t*)abp;

    // attn1: BM=32, NFB=128, 256 thr, TPI=1, 4 CTAs/SM
    // attn2: BM=16, NFB=64, 128 thr, TPI=2, 5 CTAs/SM
    const int SM1 = 2 * (128 * 128) + 2 * (32 * 128) + 256;       // 41216 bytes
    const int SM2 = 2 * (2 * 64 * 128) + 2 * (2 * 16 * 128) + 256; // 41216 bytes
    cudaFuncSetAttribute((const void*)attn_mma<FH, 128, 32, 256, 1, 4, false>,
                         cudaFuncAttributeMaxDynamicSharedMemorySize, SM1);
    cudaFuncSetAttribute((const void*)attn_mma<FOUT, 64, 16, 128, 2, 5, true>,
                         cudaFuncAttributeMaxDynamicSharedMemorySize, SM2);

    // Layer 1  (attn_mma is the 4th launch -> gets profiled by ncu)
    gemm_bias<<<dim3(FH / 64, NN / 128), 256>>>(x, W1, b1, h1, NN, FH, FIN);
    transpose_pack<<<dim3(NN / 32, FH / 32, 2), 256>>>(h1, h1T, FH, adj, abits);
    st_kernel<FH><<<NN / 8, 256>>>(h1, a1, s1, t1, tmaxi);
    attn_mma<FH, 128, 32, 256, 1, 4, false><<<(NN / 32) * 2, 256, SM1>>>(
        h1T, abits, s1, t1, ab1, tmaxi, y1);

    // Layer 2
    gemm_bias<<<dim3(FOUT / 64, NN / 128), 256>>>(y1, W2, b2, h2, NN, FOUT, FH);
    transpose_pack<<<dim3(NN / 32, FOUT / 32, 1), 256>>>(h2, h2T, FOUT, adj, abits);
    st_kernel<FOUT><<<NN / 8, 256>>>(h2, a2, s2, t2, tmaxi + 1);
    attn_mma<FOUT, 64, 16, 128, 2, 5, true><<<NN / 16, 128, SM2>>>(
        h2T, abits, s2, t2, ab2, tmaxi + 1, out);
}